// round 3
// baseline (speedup 1.0000x reference)
#include <cuda_runtime.h>
#include <math.h>

// Problem constants
#define Bb 2
#define Ss 2048
#define DM 1024
#define Hh 16
#define DKh 64
#define MTOK (Bb*Ss)                           // 4096
#define NROWS (Bb*Hh*Ss)                       // 65536 attention rows
#define NKT (Ss/128)                           // 16 k-tiles per row
#define OUT_ELEMS ((size_t)Bb*Ss*DM)           // 4,194,304
#define ATTN_ELEMS ((size_t)Bb*Hh*Ss*Ss)       // 134,217,728

typedef unsigned long long ull;

// Scratch (static device globals; no allocation allowed)
__device__ float g_qh[MTOK*DM];
__device__ float g_kh[MTOK*DM];
__device__ float g_vh[MTOK*DM];
__device__ float g_oh[MTOK*DM];
__device__ float g_y [MTOK*DM];
__device__ float g_smax[NKT*NROWS];
__device__ float g_ssum[NKT*NROWS];
__device__ float g_rmax[NROWS];
__device__ float g_rinv[NROWS];

// ---------------------------------------------------------------------------
// Packed f32x2 helpers (Blackwell FFMA2)
// ---------------------------------------------------------------------------
__device__ __forceinline__ ull fma2(ull a, ull b, ull c) {
    ull d;
    asm("fma.rn.f32x2 %0, %1, %2, %3;" : "=l"(d) : "l"(a), "l"(b), "l"(c));
    return d;
}
__device__ __forceinline__ ull pack2(float x, float y) {
    union { float2 f; ull u; } cv;
    cv.f = make_float2(x, y);
    return cv.u;
}
__device__ __forceinline__ float sum2(ull v) {
    union { float2 f; ull u; } cv;
    cv.u = v;
    return cv.f.x + cv.f.y;
}

// ---------------------------------------------------------------------------
// 128x128 SGEMM with FFMA2, BK=16 (8 k-pairs), 256 threads, 8x8 f32 per thread.
// C[M,N] = X[M,K]*W[K,N] + bias[N] (+ optional R). Lanes packed along K.
// ---------------------------------------------------------------------------
__global__ void __launch_bounds__(256)
gemm128(const float* __restrict__ X, const float* __restrict__ W,
        const float* __restrict__ bias, const float* __restrict__ R,
        float* __restrict__ C, int M, int N, int K)
{
    __shared__ __align__(16) ull sA2[8][130];   // [kpair][m]
    __shared__ __align__(16) ull sB2[8][130];   // [kpair][n]
    const int bm = blockIdx.y * 128;
    const int bn = blockIdx.x * 128;
    const int tid = threadIdx.x;
    const int tx = tid & 15, ty = tid >> 4;
    ull acc2[8][8] = {};

    for (int k0 = 0; k0 < K; k0 += 16) {
        // A: 512 float4 tasks (2/thread). float4 covers k-pairs p, p+1 for row m.
        #pragma unroll
        for (int i = 0; i < 2; ++i) {
            int e = tid + i * 256;
            int m = e >> 2, p = (e & 3) * 2;
            float4 v = *(const float4*)&X[(size_t)(bm + m) * K + k0 + p * 2];
            sA2[p  ][m] = pack2(v.x, v.y);
            sA2[p+1][m] = pack2(v.z, v.w);
        }
        // B: rows k0+2*kp, k0+2*kp+1, 4 cols per thread.
        {
            int kp = tid >> 5, ng = (tid & 31) * 4;
            const float* w0 = &W[(size_t)(k0 + kp * 2) * N + bn + ng];
            float4 r0 = *(const float4*)w0;
            float4 r1 = *(const float4*)(w0 + N);
            sB2[kp][ng+0] = pack2(r0.x, r1.x);
            sB2[kp][ng+1] = pack2(r0.y, r1.y);
            sB2[kp][ng+2] = pack2(r0.z, r1.z);
            sB2[kp][ng+3] = pack2(r0.w, r1.w);
        }
        __syncthreads();
        #pragma unroll
        for (int kp = 0; kp < 8; ++kp) {
            ull a2[8], b2[8];
            #pragma unroll
            for (int g = 0; g < 4; ++g) {
                ulonglong2 t = *(const ulonglong2*)&sA2[kp][ty * 8 + g * 2];
                a2[2*g] = t.x; a2[2*g+1] = t.y;
            }
            #pragma unroll
            for (int g = 0; g < 4; ++g) {
                ulonglong2 t = *(const ulonglong2*)&sB2[kp][tx * 2 + 32 * g];
                b2[2*g] = t.x; b2[2*g+1] = t.y;
            }
            #pragma unroll
            for (int i = 0; i < 8; ++i)
                #pragma unroll
                for (int j = 0; j < 8; ++j)
                    acc2[i][j] = fma2(a2[i], b2[j], acc2[i][j]);
        }
        __syncthreads();
    }

    #pragma unroll
    for (int i = 0; i < 8; ++i) {
        int m = bm + ty * 8 + i;
        #pragma unroll
        for (int g = 0; g < 4; ++g) {
            int n = bn + tx * 2 + 32 * g;
            float2 bs = *(const float2*)&bias[n];
            float2 o;
            o.x = sum2(acc2[i][2*g  ]) + bs.x;
            o.y = sum2(acc2[i][2*g+1]) + bs.y;
            if (R) {
                float2 r = *(const float2*)&R[(size_t)m * N + n];
                o.x += r.x; o.y += r.y;
            }
            *(float2*)&C[(size_t)m * N + n] = o;
        }
    }
}

// ---------------------------------------------------------------------------
// Attention scores 128x128, Dh=64, FFMA2. Both operands k-contiguous in gmem.
// Writes raw scaled+masked scores + per-(row,tile) softmax partials.
// ---------------------------------------------------------------------------
__global__ void __launch_bounds__(256)
attn_scores(const float* __restrict__ qh, const float* __restrict__ kh,
            const unsigned char* __restrict__ mask, float* __restrict__ P)
{
    const int bh = blockIdx.z;
    const int b = bh >> 4, h = bh & 15;
    const int bq = blockIdx.y * 128;
    const int bk = blockIdx.x * 128;
    const int tid = threadIdx.x;
    const int tx = tid & 15, ty = tid >> 4;

    __shared__ __align__(16) ull sQ2[8][130];
    __shared__ __align__(16) ull sK2[8][130];
    ull acc2[8][8] = {};

    for (int k0 = 0; k0 < DKh; k0 += 16) {
        #pragma unroll
        for (int i = 0; i < 2; ++i) {
            int e = tid + i * 256;
            int m = e >> 2, p = (e & 3) * 2;
            float4 v = *(const float4*)&qh[(size_t)(b*Ss + bq + m) * DM + h*DKh + k0 + p*2];
            sQ2[p  ][m] = pack2(v.x, v.y);
            sQ2[p+1][m] = pack2(v.z, v.w);
            float4 w = *(const float4*)&kh[(size_t)(b*Ss + bk + m) * DM + h*DKh + k0 + p*2];
            sK2[p  ][m] = pack2(w.x, w.y);
            sK2[p+1][m] = pack2(w.z, w.w);
        }
        __syncthreads();
        #pragma unroll
        for (int kp = 0; kp < 8; ++kp) {
            ull a2[8], c2[8];
            #pragma unroll
            for (int g = 0; g < 4; ++g) {
                ulonglong2 t = *(const ulonglong2*)&sQ2[kp][ty * 8 + g * 2];
                a2[2*g] = t.x; a2[2*g+1] = t.y;
            }
            #pragma unroll
            for (int g = 0; g < 4; ++g) {
                ulonglong2 t = *(const ulonglong2*)&sK2[kp][tx * 2 + 32 * g];
                c2[2*g] = t.x; c2[2*g+1] = t.y;
            }
            #pragma unroll
            for (int i = 0; i < 8; ++i)
                #pragma unroll
                for (int j = 0; j < 8; ++j)
                    acc2[i][j] = fma2(a2[i], c2[j], acc2[i][j]);
        }
        __syncthreads();
    }

    const float scale = 0.125f;
    #pragma unroll
    for (int i = 0; i < 8; ++i) {
        int q = bq + ty * 8 + i;
        const unsigned char* mrow = &mask[((size_t)b * Ss + q) * Ss + bk];
        float s[8];
        #pragma unroll
        for (int g = 0; g < 4; ++g) {
            int c = tx * 2 + 32 * g;
            s[2*g  ] = mrow[c  ] ? -INFINITY : sum2(acc2[i][2*g  ]) * scale;
            s[2*g+1] = mrow[c+1] ? -INFINITY : sum2(acc2[i][2*g+1]) * scale;
            *(float2*)&P[((size_t)bh * Ss + q) * Ss + bk + c] = make_float2(s[2*g], s[2*g+1]);
        }
        float mx = s[0];
        #pragma unroll
        for (int j = 1; j < 8; ++j) mx = fmaxf(mx, s[j]);
        #pragma unroll
        for (int off = 8; off > 0; off >>= 1)
            mx = fmaxf(mx, __shfl_xor_sync(0xffffffffu, mx, off));
        float sum = 0.f;
        if (mx != -INFINITY) {
            #pragma unroll
            for (int j = 0; j < 8; ++j) sum += __expf(s[j] - mx);
        }
        #pragma unroll
        for (int off = 8; off > 0; off >>= 1)
            sum += __shfl_xor_sync(0xffffffffu, sum, off);
        if (tx == 0) {
            size_t ridx = (size_t)blockIdx.x * NROWS + (size_t)bh * Ss + q;
            g_smax[ridx] = mx;
            g_ssum[ridx] = sum;
        }
    }
}

// ---------------------------------------------------------------------------
// Combine per-tile stats into per-row (max, 1/sum).
// ---------------------------------------------------------------------------
__global__ void __launch_bounds__(256)
reduce_stats()
{
    int r = blockIdx.x * 256 + threadIdx.x;
    float m = -INFINITY;
    #pragma unroll
    for (int t = 0; t < NKT; ++t) m = fmaxf(m, g_smax[(size_t)t * NROWS + r]);
    float sum = 0.f;
    #pragma unroll
    for (int t = 0; t < NKT; ++t) {
        float gm = g_smax[(size_t)t * NROWS + r];
        if (gm != -INFINITY)
            sum += g_ssum[(size_t)t * NROWS + r] * __expf(gm - m);
    }
    g_rmax[r] = m;
    g_rinv[r] = 1.0f / sum;
}

// ---------------------------------------------------------------------------
// PV with fused exp-normalize + in-place attn write. 128q x 64d per block,
// 128 threads, 8x8 f32 per thread, FFMA2 k-packed.
// ---------------------------------------------------------------------------
__global__ void __launch_bounds__(128)
attn_pv(float* __restrict__ P, const float* __restrict__ vh,
        float* __restrict__ O)
{
    const int bh = blockIdx.y;
    const int b = bh >> 4, h = bh & 15;
    const int bq = blockIdx.x * 128;
    const int tid = threadIdx.x;
    const int tx = tid & 7, ty = tid >> 3;

    __shared__ __align__(16) ull sP2[8][130];
    __shared__ __align__(16) ull sV2[8][66];
    __shared__ float srm[128], sri[128];

    {
        int r = bh * Ss + bq + tid;
        srm[tid] = g_rmax[r];
        sri[tid] = g_rinv[r];
    }
    __syncthreads();

    ull acc2[8][8] = {};

    for (int k0 = 0; k0 < Ss; k0 += 16) {
        #pragma unroll
        for (int i = 0; i < 4; ++i) {
            int e = tid + i * 128;
            int m = e >> 2, p = (e & 3) * 2;
            float* paddr = &P[((size_t)bh * Ss + bq + m) * Ss + k0 + p * 2];
            float4 v = *(const float4*)paddr;
            float mr = srm[m], ir = sri[m];
            v.x = __expf(v.x - mr) * ir;
            v.y = __expf(v.y - mr) * ir;
            v.z = __expf(v.z - mr) * ir;
            v.w = __expf(v.w - mr) * ir;
            *(float4*)paddr = v;                 // final normalized attn
            sP2[p  ][m] = pack2(v.x, v.y);
            sP2[p+1][m] = pack2(v.z, v.w);
        }
        {
            int kp = tid >> 4, ng = (tid & 15) * 4;
            const float* v0 = &vh[(size_t)(b*Ss + k0 + kp*2) * DM + h*DKh + ng];
            float4 r0 = *(const float4*)v0;
            float4 r1 = *(const float4*)(v0 + DM);
            sV2[kp][ng+0] = pack2(r0.x, r1.x);
            sV2[kp][ng+1] = pack2(r0.y, r1.y);
            sV2[kp][ng+2] = pack2(r0.z, r1.z);
            sV2[kp][ng+3] = pack2(r0.w, r1.w);
        }
        __syncthreads();
        #pragma unroll
        for (int kp = 0; kp < 8; ++kp) {
            ull a2[8], c2[8];
            #pragma unroll
            for (int g = 0; g < 4; ++g) {
                ulonglong2 t = *(const ulonglong2*)&sP2[kp][ty * 8 + g * 2];
                a2[2*g] = t.x; a2[2*g+1] = t.y;
            }
            #pragma unroll
            for (int g = 0; g < 4; ++g) {
                ulonglong2 t = *(const ulonglong2*)&sV2[kp][tx * 2 + 16 * g];
                c2[2*g] = t.x; c2[2*g+1] = t.y;
            }
            #pragma unroll
            for (int i = 0; i < 8; ++i)
                #pragma unroll
                for (int j = 0; j < 8; ++j)
                    acc2[i][j] = fma2(a2[i], c2[j], acc2[i][j]);
        }
        __syncthreads();
    }

    #pragma unroll
    for (int i = 0; i < 8; ++i) {
        int q = bq + ty * 8 + i;
        #pragma unroll
        for (int g = 0; g < 4; ++g) {
            int d = tx * 2 + 16 * g;
            float2 o;
            o.x = sum2(acc2[i][2*g  ]);
            o.y = sum2(acc2[i][2*g+1]);
            *(float2*)&O[(size_t)(b*Ss + q) * DM + h*DKh + d] = o;
        }
    }
}

// ---------------------------------------------------------------------------
// LayerNorm per row of 1024
// ---------------------------------------------------------------------------
__global__ void __launch_bounds__(256)
layernorm(const float* __restrict__ Xin, const float* __restrict__ gamma,
          const float* __restrict__ beta, float* __restrict__ out)
{
    const float* x = Xin + (size_t)blockIdx.x * DM;
    float* o = out + (size_t)blockIdx.x * DM;
    const int tid = threadIdx.x;
    __shared__ float r1[256], r2[256];

    float v[4], s = 0.f, sq = 0.f;
    #pragma unroll
    for (int i = 0; i < 4; ++i) {
        v[i] = x[tid + i * 256];
        s += v[i];
        sq += v[i] * v[i];
    }
    r1[tid] = s; r2[tid] = sq; __syncthreads();
    for (int st = 128; st > 0; st >>= 1) {
        if (tid < st) { r1[tid] += r1[tid + st]; r2[tid] += r2[tid + st]; }
        __syncthreads();
    }
    float mean = r1[0] * (1.0f / DM);
    float var  = r2[0] * (1.0f / DM) - mean * mean;
    float inv = rsqrtf(var + 1e-5f);
    #pragma unroll
    for (int i = 0; i < 4; ++i) {
        int c = tid + i * 256;
        o[c] = (v[i] - mean) * inv * gamma[c] + beta[c];
    }
}

// ---------------------------------------------------------------------------
extern "C" void kernel_launch(void* const* d_in, const int* in_sizes, int n_in,
                              void* d_out, int out_size)
{
    const float* q    = (const float*)d_in[0];
    const float* k    = (const float*)d_in[1];
    const float* v    = (const float*)d_in[2];
    const unsigned char* mask = (const unsigned char*)d_in[3];
    const float* Wq   = (const float*)d_in[4];
    const float* bq   = (const float*)d_in[5];
    const float* Wk   = (const float*)d_in[6];
    const float* bk   = (const float*)d_in[7];
    const float* Wv   = (const float*)d_in[8];
    const float* bv   = (const float*)d_in[9];
    const float* Wo   = (const float*)d_in[10];
    const float* bo   = (const float*)d_in[11];
    const float* ln_g = (const float*)d_in[12];
    const float* ln_b = (const float*)d_in[13];

    float* outp = (float*)d_out;
    float* attn = outp + OUT_ELEMS;

    float *qh, *kh, *vh, *oh, *y;
    cudaGetSymbolAddress((void**)&qh, g_qh);
    cudaGetSymbolAddress((void**)&kh, g_kh);
    cudaGetSymbolAddress((void**)&vh, g_vh);
    cudaGetSymbolAddress((void**)&oh, g_oh);
    cudaGetSymbolAddress((void**)&y,  g_y);

    dim3 gProj(DM / 128, MTOK / 128);              // (8, 32)
    gemm128<<<gProj, 256>>>(q, Wq, bq, nullptr, qh, MTOK, DM, DM);
    gemm128<<<gProj, 256>>>(k, Wk, bk, nullptr, kh, MTOK, DM, DM);
    gemm128<<<gProj, 256>>>(v, Wv, bv, nullptr, vh, MTOK, DM, DM);

    dim3 gScores(Ss / 128, Ss / 128, Bb * Hh);     // (16, 16, 32)
    attn_scores<<<gScores, 256>>>(qh, kh, mask, attn);

    reduce_stats<<<NROWS / 256, 256>>>();

    dim3 gPV(Ss / 128, Bb * Hh);                   // (16, 32)
    attn_pv<<<gPV, 128>>>(attn, vh, oh);

    gemm128<<<gProj, 256>>>(oh, Wo, bo, q, y, MTOK, DM, DM);

    layernorm<<<MTOK, 256>>>(y, ln_g, ln_b, outp);
}

// round 4
// speedup vs baseline: 1.0805x; 1.0805x over previous
#include <cuda_runtime.h>
#include <cuda_bf16.h>
#include <math.h>

// Problem constants
#define Bb 2
#define Ss 2048
#define DM 1024
#define Hh 16
#define DKh 64
#define MTOK (Bb*Ss)                           // 4096
#define NROWS (Bb*Hh*Ss)                       // 65536 attention rows
#define NKT (Ss/128)                           // 16 k-tiles per row
#define OUT_ELEMS ((size_t)Bb*Ss*DM)
#define ATTN_ELEMS ((size_t)Bb*Hh*Ss*Ss)

#define STR 40                                  // smem bf16 row stride (80B, conflict-free)

typedef unsigned int u32;

// Scratch
__device__ float g_qh[MTOK*DM];
__device__ float g_kh[MTOK*DM];
__device__ float g_vh[MTOK*DM];
__device__ float g_oh[MTOK*DM];
__device__ float g_y [MTOK*DM];
__device__ float g_smax[NKT*NROWS];
__device__ float g_ssum[NKT*NROWS];
__device__ float g_rmax[NROWS];
__device__ float g_rinv[NROWS];

// ---------------------------------------------------------------------------
// MMA helpers
// ---------------------------------------------------------------------------
__device__ __forceinline__ u32 smaddr(const void* p) {
    return (u32)__cvta_generic_to_shared(p);
}
__device__ __forceinline__ void ldsm4(u32& r0, u32& r1, u32& r2, u32& r3, u32 a) {
    asm volatile("ldmatrix.sync.aligned.m8n8.x4.shared.b16 {%0,%1,%2,%3},[%4];"
                 : "=r"(r0), "=r"(r1), "=r"(r2), "=r"(r3) : "r"(a));
}
__device__ __forceinline__ void mmabf(float* d, const u32* a, u32 b0, u32 b1) {
    asm volatile(
        "mma.sync.aligned.m16n8k16.row.col.f32.bf16.bf16.f32 "
        "{%0,%1,%2,%3},{%4,%5,%6,%7},{%8,%9},{%0,%1,%2,%3};"
        : "+f"(d[0]), "+f"(d[1]), "+f"(d[2]), "+f"(d[3])
        : "r"(a[0]), "r"(a[1]), "r"(a[2]), "r"(a[3]), "r"(b0), "r"(b1));
}
__device__ __forceinline__ void split1(float x, __nv_bfloat16& h, __nv_bfloat16& l) {
    h = __float2bfloat16(x);
    l = __float2bfloat16(x - __bfloat162float(h));
}
// store 4 consecutive k-values (hi & lo) at row-major smem position
__device__ __forceinline__ void cvst4(__nv_bfloat16* ph, __nv_bfloat16* pl, float4 v) {
    __nv_bfloat16 h0,h1,h2,h3,l0,l1,l2,l3;
    split1(v.x,h0,l0); split1(v.y,h1,l1); split1(v.z,h2,l2); split1(v.w,h3,l3);
    *(__nv_bfloat162*)(ph)   = __halves2bfloat162(h0,h1);
    *(__nv_bfloat162*)(ph+2) = __halves2bfloat162(h2,h3);
    *(__nv_bfloat162*)(pl)   = __halves2bfloat162(l0,l1);
    *(__nv_bfloat162*)(pl+2) = __halves2bfloat162(l2,l3);
}

// ---------------------------------------------------------------------------
// GEMM: C[M,N] = X[M,K] * W[K,N] + bias (+R). 128x128 tile, 256 thr, bf16x3 mma.
// X k-contig; W n-contig (transposed into smem [n][k]).
// ---------------------------------------------------------------------------
__global__ void __launch_bounds__(256)
gemm_t3(const float* __restrict__ X, const float* __restrict__ W,
        const float* __restrict__ bias, const float* __restrict__ R,
        float* __restrict__ C, int M, int N, int K)
{
    __shared__ __nv_bfloat16 sAh[128*STR], sAl[128*STR];
    __shared__ __nv_bfloat16 sBh[128*STR], sBl[128*STR];
    const int tid = threadIdx.x, lane = tid & 31, wid = tid >> 5;
    const int wm = wid & 3, wn = wid >> 2;
    const int bm = blockIdx.y * 128, bn = blockIdx.x * 128;

    float acc[2][8][4] = {};

    const int arow = lane & 15;
    const int achk = lane >> 4;
    const int brow = ((lane >> 4) << 3) + (lane & 7);
    const int bchk = (lane >> 3) & 1;

    for (int k0 = 0; k0 < K; k0 += 32) {
        #pragma unroll
        for (int i = 0; i < 4; ++i) {
            int e = tid + i * 256;
            int m = e >> 3, kg = (e & 7) * 4;
            float4 v = *(const float4*)&X[(size_t)(bm + m) * K + k0 + kg];
            cvst4(&sAh[m*STR+kg], &sAl[m*STR+kg], v);
        }
        #pragma unroll
        for (int i = 0; i < 4; ++i) {
            int e = tid + i * 256;
            int kk = e >> 5, ng = (e & 31) * 4;
            float4 v = *(const float4*)&W[(size_t)(k0 + kk) * N + bn + ng];
            split1(v.x, sBh[(ng+0)*STR+kk], sBl[(ng+0)*STR+kk]);
            split1(v.y, sBh[(ng+1)*STR+kk], sBl[(ng+1)*STR+kk]);
            split1(v.z, sBh[(ng+2)*STR+kk], sBl[(ng+2)*STR+kk]);
            split1(v.w, sBh[(ng+3)*STR+kk], sBl[(ng+3)*STR+kk]);
        }
        __syncthreads();
        #pragma unroll
        for (int kc = 0; kc < 2; ++kc) {
            u32 ah[2][4], al[2][4];
            #pragma unroll
            for (int mt = 0; mt < 2; ++mt) {
                int row = wm*32 + mt*16 + arow;
                u32 off = row*(STR*2) + (2*kc + achk)*16;
                ldsm4(ah[mt][0],ah[mt][1],ah[mt][2],ah[mt][3], smaddr(sAh)+off);
                ldsm4(al[mt][0],al[mt][1],al[mt][2],al[mt][3], smaddr(sAl)+off);
            }
            #pragma unroll
            for (int ntp = 0; ntp < 4; ++ntp) {
                int row = wn*64 + ntp*16 + brow;
                u32 off = row*(STR*2) + (2*kc + bchk)*16;
                u32 bh0,bh1,bh2,bh3, bl0,bl1,bl2,bl3;
                ldsm4(bh0,bh1,bh2,bh3, smaddr(sBh)+off);
                ldsm4(bl0,bl1,bl2,bl3, smaddr(sBl)+off);
                #pragma unroll
                for (int mt = 0; mt < 2; ++mt) {
                    mmabf(acc[mt][2*ntp],   ah[mt], bh0, bh1);
                    mmabf(acc[mt][2*ntp],   al[mt], bh0, bh1);
                    mmabf(acc[mt][2*ntp],   ah[mt], bl0, bl1);
                    mmabf(acc[mt][2*ntp+1], ah[mt], bh2, bh3);
                    mmabf(acc[mt][2*ntp+1], al[mt], bh2, bh3);
                    mmabf(acc[mt][2*ntp+1], ah[mt], bl2, bl3);
                }
            }
        }
        __syncthreads();
    }

    #pragma unroll
    for (int mt = 0; mt < 2; ++mt) {
        int r0 = bm + wm*32 + mt*16 + (lane >> 2);
        #pragma unroll
        for (int nt = 0; nt < 8; ++nt) {
            int n = bn + wn*64 + nt*8 + (lane & 3)*2;
            float2 bs = *(const float2*)&bias[n];
            float* d = acc[mt][nt];
            float2 o0 = make_float2(d[0]+bs.x, d[1]+bs.y);
            float2 o1 = make_float2(d[2]+bs.x, d[3]+bs.y);
            if (R) {
                float2 ra = *(const float2*)&R[(size_t)r0*N + n];
                float2 rb = *(const float2*)&R[(size_t)(r0+8)*N + n];
                o0.x += ra.x; o0.y += ra.y; o1.x += rb.x; o1.y += rb.y;
            }
            *(float2*)&C[(size_t)r0*N + n] = o0;
            *(float2*)&C[(size_t)(r0+8)*N + n] = o1;
        }
    }
}

// ---------------------------------------------------------------------------
// Scores: P = scale*Q·K^T (masked), + per-(row,128-tile) softmax partials.
// 128x128 tile, K=64. Both operands k-major.
// ---------------------------------------------------------------------------
__global__ void __launch_bounds__(256)
attn_scores(const float* __restrict__ qh, const float* __restrict__ kh,
            const unsigned char* __restrict__ mask, float* __restrict__ P)
{
    __shared__ __nv_bfloat16 sAh[128*STR], sAl[128*STR];
    __shared__ __nv_bfloat16 sBh[128*STR], sBl[128*STR];
    __shared__ float sM[128][2], sS[128][2];

    const int tid = threadIdx.x, lane = tid & 31, wid = tid >> 5;
    const int wm = wid & 3, wn = wid >> 2;
    const int bh = blockIdx.z, b = bh >> 4, h = bh & 15;
    const int bq = blockIdx.y * 128, bk = blockIdx.x * 128;

    float acc[2][8][4] = {};
    const int arow = lane & 15;
    const int achk = lane >> 4;
    const int brow = ((lane >> 4) << 3) + (lane & 7);
    const int bchk = (lane >> 3) & 1;

    for (int k0 = 0; k0 < DKh; k0 += 32) {
        #pragma unroll
        for (int i = 0; i < 4; ++i) {
            int e = tid + i * 256;
            int m = e >> 3, kg = (e & 7) * 4;
            float4 v = *(const float4*)&qh[(size_t)(b*Ss + bq + m)*DM + h*DKh + k0 + kg];
            cvst4(&sAh[m*STR+kg], &sAl[m*STR+kg], v);
            float4 w = *(const float4*)&kh[(size_t)(b*Ss + bk + m)*DM + h*DKh + k0 + kg];
            cvst4(&sBh[m*STR+kg], &sBl[m*STR+kg], w);
        }
        __syncthreads();
        #pragma unroll
        for (int kc = 0; kc < 2; ++kc) {
            u32 ah[2][4], al[2][4];
            #pragma unroll
            for (int mt = 0; mt < 2; ++mt) {
                int row = wm*32 + mt*16 + arow;
                u32 off = row*(STR*2) + (2*kc + achk)*16;
                ldsm4(ah[mt][0],ah[mt][1],ah[mt][2],ah[mt][3], smaddr(sAh)+off);
                ldsm4(al[mt][0],al[mt][1],al[mt][2],al[mt][3], smaddr(sAl)+off);
            }
            #pragma unroll
            for (int ntp = 0; ntp < 4; ++ntp) {
                int row = wn*64 + ntp*16 + brow;
                u32 off = row*(STR*2) + (2*kc + bchk)*16;
                u32 bh0,bh1,bh2,bh3, bl0,bl1,bl2,bl3;
                ldsm4(bh0,bh1,bh2,bh3, smaddr(sBh)+off);
                ldsm4(bl0,bl1,bl2,bl3, smaddr(sBl)+off);
                #pragma unroll
                for (int mt = 0; mt < 2; ++mt) {
                    mmabf(acc[mt][2*ntp],   ah[mt], bh0, bh1);
                    mmabf(acc[mt][2*ntp],   al[mt], bh0, bh1);
                    mmabf(acc[mt][2*ntp],   ah[mt], bl0, bl1);
                    mmabf(acc[mt][2*ntp+1], ah[mt], bh2, bh3);
                    mmabf(acc[mt][2*ntp+1], al[mt], bh2, bh3);
                    mmabf(acc[mt][2*ntp+1], ah[mt], bl2, bl3);
                }
            }
        }
        __syncthreads();
    }

    const float scale = 0.125f;
    #pragma unroll
    for (int mt = 0; mt < 2; ++mt) {
        int rb = wm*32 + mt*16 + (lane >> 2);
        const unsigned char* mk0 = mask + ((size_t)(b*Ss + bq + rb))*Ss + bk + wn*64;
        const unsigned char* mk1 = mk0 + (size_t)8*Ss;
        float mx0 = -INFINITY, mx1 = -INFINITY;
        #pragma unroll
        for (int nt = 0; nt < 8; ++nt) {
            int c = nt*8 + (lane & 3)*2;
            float* d = acc[mt][nt];
            d[0] = mk0[c]   ? -INFINITY : d[0]*scale;
            d[1] = mk0[c+1] ? -INFINITY : d[1]*scale;
            d[2] = mk1[c]   ? -INFINITY : d[2]*scale;
            d[3] = mk1[c+1] ? -INFINITY : d[3]*scale;
            mx0 = fmaxf(mx0, fmaxf(d[0], d[1]));
            mx1 = fmaxf(mx1, fmaxf(d[2], d[3]));
        }
        mx0 = fmaxf(mx0, __shfl_xor_sync(0xffffffffu, mx0, 1));
        mx0 = fmaxf(mx0, __shfl_xor_sync(0xffffffffu, mx0, 2));
        mx1 = fmaxf(mx1, __shfl_xor_sync(0xffffffffu, mx1, 1));
        mx1 = fmaxf(mx1, __shfl_xor_sync(0xffffffffu, mx1, 2));

        float sm0 = 0.f, sm1 = 0.f;
        float* Pr0 = P + ((size_t)bh*Ss + bq + rb)*Ss + bk + wn*64;
        float* Pr1 = Pr0 + (size_t)8*Ss;
        #pragma unroll
        for (int nt = 0; nt < 8; ++nt) {
            int c = nt*8 + (lane & 3)*2;
            float* d = acc[mt][nt];
            *(float2*)(Pr0 + c) = make_float2(d[0], d[1]);
            *(float2*)(Pr1 + c) = make_float2(d[2], d[3]);
            if (mx0 != -INFINITY) sm0 += __expf(d[0]-mx0) + __expf(d[1]-mx0);
            if (mx1 != -INFINITY) sm1 += __expf(d[2]-mx1) + __expf(d[3]-mx1);
        }
        sm0 += __shfl_xor_sync(0xffffffffu, sm0, 1);
        sm0 += __shfl_xor_sync(0xffffffffu, sm0, 2);
        sm1 += __shfl_xor_sync(0xffffffffu, sm1, 1);
        sm1 += __shfl_xor_sync(0xffffffffu, sm1, 2);
        if ((lane & 3) == 0) {
            sM[rb][wn] = mx0;  sS[rb][wn] = sm0;
            sM[rb+8][wn] = mx1; sS[rb+8][wn] = sm1;
        }
    }
    __syncthreads();
    if (tid < 128) {
        float m0 = sM[tid][0], m1 = sM[tid][1];
        float m = fmaxf(m0, m1), s = 0.f;
        if (m0 != -INFINITY) s += sS[tid][0] * __expf(m0 - m);
        if (m1 != -INFINITY) s += sS[tid][1] * __expf(m1 - m);
        size_t ridx = (size_t)blockIdx.x * NROWS + (size_t)bh*Ss + bq + tid;
        g_smax[ridx] = m;
        g_ssum[ridx] = s;
    }
}

// ---------------------------------------------------------------------------
// Combine per-tile stats into per-row (max, 1/sum).
// ---------------------------------------------------------------------------
__global__ void __launch_bounds__(256)
reduce_stats()
{
    int r = blockIdx.x * 256 + threadIdx.x;
    float m = -INFINITY;
    #pragma unroll
    for (int t = 0; t < NKT; ++t) m = fmaxf(m, g_smax[(size_t)t*NROWS + r]);
    float sum = 0.f;
    #pragma unroll
    for (int t = 0; t < NKT; ++t) {
        float gm = g_smax[(size_t)t*NROWS + r];
        if (gm != -INFINITY) sum += g_ssum[(size_t)t*NROWS + r] * __expf(gm - m);
    }
    g_rmax[r] = m;
    g_rinv[r] = 1.0f / sum;
}

// ---------------------------------------------------------------------------
// PV: p = exp(s-m)*inv (written back in place = final attn), O = p @ V.
// 128q x 64d tile, 256 thr (8 warps x 16 rows), bf16x3 mma, K=2048.
// ---------------------------------------------------------------------------
__global__ void __launch_bounds__(256)
attn_pv(float* __restrict__ P, const float* __restrict__ vh,
        float* __restrict__ O)
{
    __shared__ __nv_bfloat16 sAh[128*STR], sAl[128*STR];
    __shared__ __nv_bfloat16 sBh[64*STR], sBl[64*STR];
    __shared__ float srm[128], sri[128];

    const int tid = threadIdx.x, lane = tid & 31, wid = tid >> 5;
    const int bh = blockIdx.y, b = bh >> 4, h = bh & 15;
    const int bq = blockIdx.x * 128;

    if (tid < 128) {
        int r = bh * Ss + bq + tid;
        srm[tid] = g_rmax[r];
        sri[tid] = g_rinv[r];
    }
    __syncthreads();

    float acc[8][4] = {};
    const int arow = lane & 15;
    const int achk = lane >> 4;
    const int brow = ((lane >> 4) << 3) + (lane & 7);
    const int bchk = (lane >> 3) & 1;

    for (int k0 = 0; k0 < Ss; k0 += 32) {
        #pragma unroll
        for (int i = 0; i < 4; ++i) {
            int e = tid + i * 256;
            int m = e >> 3, kg = (e & 7) * 4;
            float* pa = &P[((size_t)bh*Ss + bq + m)*Ss + k0 + kg];
            float4 v = *(const float4*)pa;
            float mr = srm[m], ir = sri[m];
            v.x = __expf(v.x - mr) * ir;
            v.y = __expf(v.y - mr) * ir;
            v.z = __expf(v.z - mr) * ir;
            v.w = __expf(v.w - mr) * ir;
            *(float4*)pa = v;                      // final normalized attn
            cvst4(&sAh[m*STR+kg], &sAl[m*STR+kg], v);
        }
        #pragma unroll
        for (int i = 0; i < 2; ++i) {
            int e = tid + i * 256;
            int kk = e >> 4, ng = (e & 15) * 4;
            float4 v = *(const float4*)&vh[(size_t)(b*Ss + k0 + kk)*DM + h*DKh + ng];
            split1(v.x, sBh[(ng+0)*STR+kk], sBl[(ng+0)*STR+kk]);
            split1(v.y, sBh[(ng+1)*STR+kk], sBl[(ng+1)*STR+kk]);
            split1(v.z, sBh[(ng+2)*STR+kk], sBl[(ng+2)*STR+kk]);
            split1(v.w, sBh[(ng+3)*STR+kk], sBl[(ng+3)*STR+kk]);
        }
        __syncthreads();
        #pragma unroll
        for (int kc = 0; kc < 2; ++kc) {
            u32 ah[4], al[4];
            {
                int row = wid*16 + arow;
                u32 off = row*(STR*2) + (2*kc + achk)*16;
                ldsm4(ah[0],ah[1],ah[2],ah[3], smaddr(sAh)+off);
                ldsm4(al[0],al[1],al[2],al[3], smaddr(sAl)+off);
            }
            #pragma unroll
            for (int ntp = 0; ntp < 4; ++ntp) {
                int row = ntp*16 + brow;
                u32 off = row*(STR*2) + (2*kc + bchk)*16;
                u32 bh0,bh1,bh2,bh3, bl0,bl1,bl2,bl3;
                ldsm4(bh0,bh1,bh2,bh3, smaddr(sBh)+off);
                ldsm4(bl0,bl1,bl2,bl3, smaddr(sBl)+off);
                mmabf(acc[2*ntp],   ah, bh0, bh1);
                mmabf(acc[2*ntp],   al, bh0, bh1);
                mmabf(acc[2*ntp],   ah, bl0, bl1);
                mmabf(acc[2*ntp+1], ah, bh2, bh3);
                mmabf(acc[2*ntp+1], al, bh2, bh3);
                mmabf(acc[2*ntp+1], ah, bl2, bl3);
            }
        }
        __syncthreads();
    }

    int r0 = bq + wid*16 + (lane >> 2);
    #pragma unroll
    for (int nt = 0; nt < 8; ++nt) {
        int d = nt*8 + (lane & 3)*2;
        *(float2*)&O[(size_t)(b*Ss + r0)*DM + h*DKh + d] =
            make_float2(acc[nt][0], acc[nt][1]);
        *(float2*)&O[(size_t)(b*Ss + r0 + 8)*DM + h*DKh + d] =
            make_float2(acc[nt][2], acc[nt][3]);
    }
}

// ---------------------------------------------------------------------------
// LayerNorm per row of 1024
// ---------------------------------------------------------------------------
__global__ void __launch_bounds__(256)
layernorm(const float* __restrict__ Xin, const float* __restrict__ gamma,
          const float* __restrict__ beta, float* __restrict__ out)
{
    const float* x = Xin + (size_t)blockIdx.x * DM;
    float* o = out + (size_t)blockIdx.x * DM;
    const int tid = threadIdx.x;
    __shared__ float r1[256], r2[256];

    float v[4], s = 0.f, sq = 0.f;
    #pragma unroll
    for (int i = 0; i < 4; ++i) {
        v[i] = x[tid + i * 256];
        s += v[i];
        sq += v[i] * v[i];
    }
    r1[tid] = s; r2[tid] = sq; __syncthreads();
    for (int st = 128; st > 0; st >>= 1) {
        if (tid < st) { r1[tid] += r1[tid + st]; r2[tid] += r2[tid + st]; }
        __syncthreads();
    }
    float mean = r1[0] * (1.0f / DM);
    float var  = r2[0] * (1.0f / DM) - mean * mean;
    float inv = rsqrtf(var + 1e-5f);
    #pragma unroll
    for (int i = 0; i < 4; ++i) {
        int c = tid + i * 256;
        o[c] = (v[i] - mean) * inv * gamma[c] + beta[c];
    }
}

// ---------------------------------------------------------------------------
extern "C" void kernel_launch(void* const* d_in, const int* in_sizes, int n_in,
                              void* d_out, int out_size)
{
    const float* q    = (const float*)d_in[0];
    const float* k    = (const float*)d_in[1];
    const float* v    = (const float*)d_in[2];
    const unsigned char* mask = (const unsigned char*)d_in[3];
    const float* Wq   = (const float*)d_in[4];
    const float* bq   = (const float*)d_in[5];
    const float* Wk   = (const float*)d_in[6];
    const float* bk   = (const float*)d_in[7];
    const float* Wv   = (const float*)d_in[8];
    const float* bv   = (const float*)d_in[9];
    const float* Wo   = (const float*)d_in[10];
    const float* bo   = (const float*)d_in[11];
    const float* ln_g = (const float*)d_in[12];
    const float* ln_b = (const float*)d_in[13];

    float* outp = (float*)d_out;
    float* attn = outp + OUT_ELEMS;

    float *qh, *kh, *vh, *oh, *y;
    cudaGetSymbolAddress((void**)&qh, g_qh);
    cudaGetSymbolAddress((void**)&kh, g_kh);
    cudaGetSymbolAddress((void**)&vh, g_vh);
    cudaGetSymbolAddress((void**)&oh, g_oh);
    cudaGetSymbolAddress((void**)&y,  g_y);

    dim3 gProj(DM / 128, MTOK / 128);              // (8, 32)
    gemm_t3<<<gProj, 256>>>(q, Wq, bq, nullptr, qh, MTOK, DM, DM);
    gemm_t3<<<gProj, 256>>>(k, Wk, bk, nullptr, kh, MTOK, DM, DM);
    gemm_t3<<<gProj, 256>>>(v, Wv, bv, nullptr, vh, MTOK, DM, DM);

    dim3 gScores(Ss / 128, Ss / 128, Bb * Hh);     // (16, 16, 32)
    attn_scores<<<gScores, 256>>>(qh, kh, mask, attn);

    reduce_stats<<<NROWS / 256, 256>>>();

    dim3 gPV(Ss / 128, Bb * Hh);                   // (16, 32)
    attn_pv<<<gPV, 256>>>(attn, vh, oh);

    gemm_t3<<<gProj, 256>>>(oh, Wo, bo, q, y, MTOK, DM, DM);

    layernorm<<<MTOK, 256>>>(y, ln_g, ln_b, outp);
}

// round 5
// speedup vs baseline: 2.1792x; 2.0169x over previous
#include <cuda_runtime.h>
#include <cuda_fp16.h>
#include <math.h>

// Problem constants
#define Bb 2
#define Ss 2048
#define DM 1024
#define Hh 16
#define DKh 64
#define MTOK (Bb*Ss)                 // 4096
#define NROWS (Bb*Hh*Ss)             // 65536
#define OUT_ELEMS ((size_t)Bb*Ss*DM)

typedef unsigned int u32;
typedef unsigned short u16;

// ---------------- device scratch (no allocation allowed) ----------------
__device__ __half g_qi_h[MTOK*DM], g_qi_l[MTOK*DM];
__device__ __half g_ki_h[MTOK*DM], g_ki_l[MTOK*DM];
__device__ __half g_vi_h[MTOK*DM], g_vi_l[MTOK*DM];
__device__ __half g_wq_h[DM*DM], g_wq_l[DM*DM];
__device__ __half g_wk_h[DM*DM], g_wk_l[DM*DM];
__device__ __half g_wv_h[DM*DM], g_wv_l[DM*DM];
__device__ __half g_wo_h[DM*DM], g_wo_l[DM*DM];
__device__ __half g_qh_h[MTOK*DM], g_qh_l[MTOK*DM];
__device__ __half g_kh_h[MTOK*DM], g_kh_l[MTOK*DM];
__device__ __half g_vh_h[MTOK*DM], g_vh_l[MTOK*DM];
__device__ __half g_oh_h[MTOK*DM], g_oh_l[MTOK*DM];
__device__ float  g_y[MTOK*DM];
__device__ float  g_rinv[NROWS];

// ---------------- helpers ----------------
__device__ __forceinline__ u32 smaddr(const void* p) {
    return (u32)__cvta_generic_to_shared(p);
}
__device__ __forceinline__ void ldsm4(u32& r0, u32& r1, u32& r2, u32& r3, u32 a) {
    asm volatile("ldmatrix.sync.aligned.m8n8.x4.shared.b16 {%0,%1,%2,%3},[%4];"
                 : "=r"(r0), "=r"(r1), "=r"(r2), "=r"(r3) : "r"(a));
}
__device__ __forceinline__ void ldsm4t(u32& r0, u32& r1, u32& r2, u32& r3, u32 a) {
    asm volatile("ldmatrix.sync.aligned.m8n8.x4.trans.shared.b16 {%0,%1,%2,%3},[%4];"
                 : "=r"(r0), "=r"(r1), "=r"(r2), "=r"(r3) : "r"(a));
}
__device__ __forceinline__ void mma16(float* d, const u32* a, u32 b0, u32 b1) {
    asm volatile(
        "mma.sync.aligned.m16n8k16.row.col.f32.f16.f16.f32 "
        "{%0,%1,%2,%3},{%4,%5,%6,%7},{%8,%9},{%0,%1,%2,%3};"
        : "+f"(d[0]), "+f"(d[1]), "+f"(d[2]), "+f"(d[3])
        : "r"(a[0]), "r"(a[1]), "r"(a[2]), "r"(a[3]), "r"(b0), "r"(b1));
}

// ---------------- split kernels ----------------
__global__ void __launch_bounds__(256)
split_f32(const float* __restrict__ src, __half* __restrict__ dh,
          __half* __restrict__ dl, int n4)
{
    int i = blockIdx.x * 256 + threadIdx.x;
    if (i >= n4) return;
    float4 v = ((const float4*)src)[i];
    __half2 h0 = __floats2half2_rn(v.x, v.y);
    __half2 h1 = __floats2half2_rn(v.z, v.w);
    float2 f0 = __half22float2(h0), f1 = __half22float2(h1);
    __half2 l0 = __floats2half2_rn(v.x - f0.x, v.y - f0.y);
    __half2 l1 = __floats2half2_rn(v.z - f1.x, v.w - f1.y);
    ((__half2*)dh)[2*i]   = h0; ((__half2*)dh)[2*i+1] = h1;
    ((__half2*)dl)[2*i]   = l0; ((__half2*)dl)[2*i+1] = l1;
}

// W[K][N] -> T[N][K] split hi/lo
__global__ void __launch_bounds__(256)
splitT_w(const float* __restrict__ W, __half* __restrict__ th,
         __half* __restrict__ tl)
{
    __shared__ float t[32][33];
    int kb = blockIdx.y * 32, nb = blockIdx.x * 32;
    int tx = threadIdx.x, ty = threadIdx.y;
    #pragma unroll
    for (int i = 0; i < 4; ++i)
        t[ty + i*8][tx] = W[(size_t)(kb + ty + i*8) * DM + nb + tx];
    __syncthreads();
    #pragma unroll
    for (int i = 0; i < 4; ++i) {
        int n = nb + ty + i*8, k = kb + tx;
        float v = t[tx][ty + i*8];
        __half h = __float2half_rn(v);
        th[(size_t)n * DM + k] = h;
        tl[(size_t)n * DM + k] = __float2half_rn(v - __half2float(h));
    }
}

// ---------------------------------------------------------------------------
// fp16 3-term GEMM: C[M,N] = (Ah+Al)[M,K] * (Bh+Bl)[N,K]^T + bias (+R)
// 128x128 tile, 256 thr. Output: either split hi/lo fp16, or fp32 (+residual).
// ---------------------------------------------------------------------------
#define SG 40   /* smem stride halves */
__global__ void __launch_bounds__(256)
gemm_h3(const __half* __restrict__ Ah, const __half* __restrict__ Al,
        const __half* __restrict__ Bh, const __half* __restrict__ Bl,
        const float* __restrict__ bias, const float* __restrict__ R,
        __half* __restrict__ Ch, __half* __restrict__ Cl,
        float* __restrict__ Cf, int M, int N, int K)
{
    __shared__ __half sAh[128*SG], sAl[128*SG], sBh[128*SG], sBl[128*SG];
    const int tid = threadIdx.x, lane = tid & 31, wid = tid >> 5;
    const int wm = wid & 3, wn = wid >> 2;
    const int bm = blockIdx.y * 128, bn = blockIdx.x * 128;
    float acc[2][8][4] = {};
    const int arow = lane & 15, achk = lane >> 4;
    const int brow = ((lane >> 4) << 3) + (lane & 7), bchk = (lane >> 3) & 1;

    for (int k0 = 0; k0 < K; k0 += 32) {
        #pragma unroll
        for (int i = 0; i < 2; ++i) {
            int e = tid + i * 256;           // 0..511
            int m = e >> 2, c = e & 3;       // 8-half chunks
            *(uint4*)&sAh[m*SG + c*8] = *(const uint4*)&Ah[(size_t)(bm+m)*K + k0 + c*8];
            *(uint4*)&sAl[m*SG + c*8] = *(const uint4*)&Al[(size_t)(bm+m)*K + k0 + c*8];
            *(uint4*)&sBh[m*SG + c*8] = *(const uint4*)&Bh[(size_t)(bn+m)*K + k0 + c*8];
            *(uint4*)&sBl[m*SG + c*8] = *(const uint4*)&Bl[(size_t)(bn+m)*K + k0 + c*8];
        }
        __syncthreads();
        #pragma unroll
        for (int kc = 0; kc < 2; ++kc) {
            u32 ah[2][4], al[2][4];
            #pragma unroll
            for (int mt = 0; mt < 2; ++mt) {
                int row = wm*32 + mt*16 + arow;
                u32 off = row*(SG*2) + (2*kc + achk)*16;
                ldsm4(ah[mt][0],ah[mt][1],ah[mt][2],ah[mt][3], smaddr(sAh)+off);
                ldsm4(al[mt][0],al[mt][1],al[mt][2],al[mt][3], smaddr(sAl)+off);
            }
            #pragma unroll
            for (int ntp = 0; ntp < 4; ++ntp) {
                int row = wn*64 + ntp*16 + brow;
                u32 off = row*(SG*2) + (2*kc + bchk)*16;
                u32 b0,b1,b2,b3, c0,c1,c2,c3;
                ldsm4(b0,b1,b2,b3, smaddr(sBh)+off);
                ldsm4(c0,c1,c2,c3, smaddr(sBl)+off);
                #pragma unroll
                for (int mt = 0; mt < 2; ++mt) {
                    mma16(acc[mt][2*ntp],   ah[mt], b0, b1);
                    mma16(acc[mt][2*ntp],   al[mt], b0, b1);
                    mma16(acc[mt][2*ntp],   ah[mt], c0, c1);
                    mma16(acc[mt][2*ntp+1], ah[mt], b2, b3);
                    mma16(acc[mt][2*ntp+1], al[mt], b2, b3);
                    mma16(acc[mt][2*ntp+1], ah[mt], c2, c3);
                }
            }
        }
        __syncthreads();
    }

    #pragma unroll
    for (int mt = 0; mt < 2; ++mt) {
        int r0 = bm + wm*32 + mt*16 + (lane >> 2);
        #pragma unroll
        for (int nt = 0; nt < 8; ++nt) {
            int n = bn + wn*64 + nt*8 + (lane & 3)*2;
            float2 bs = *(const float2*)&bias[n];
            float* d = acc[mt][nt];
            float v00 = d[0]+bs.x, v01 = d[1]+bs.y;
            float v10 = d[2]+bs.x, v11 = d[3]+bs.y;
            if (Cf) {
                float2 ra = *(const float2*)&R[(size_t)r0*N + n];
                float2 rb = *(const float2*)&R[(size_t)(r0+8)*N + n];
                *(float2*)&Cf[(size_t)r0*N + n]     = make_float2(v00+ra.x, v01+ra.y);
                *(float2*)&Cf[(size_t)(r0+8)*N + n] = make_float2(v10+rb.x, v11+rb.y);
            } else {
                __half2 h0 = __floats2half2_rn(v00, v01);
                __half2 h1 = __floats2half2_rn(v10, v11);
                float2 f0 = __half22float2(h0), f1 = __half22float2(h1);
                *(__half2*)&Ch[(size_t)r0*N + n]     = h0;
                *(__half2*)&Ch[(size_t)(r0+8)*N + n] = h1;
                *(__half2*)&Cl[(size_t)r0*N + n]     = __floats2half2_rn(v00-f0.x, v01-f0.y);
                *(__half2*)&Cl[(size_t)(r0+8)*N + n] = __floats2half2_rn(v10-f1.x, v11-f1.y);
            }
        }
    }
}

// ---------------------------------------------------------------------------
// Attention pass 1: row sums of exp(scale*Q.K^T) (masked). No score writes.
// Grid (16 q-tiles, 32 bh). 8 warps, each owns m16 rows. K-tiles of 64.
// ---------------------------------------------------------------------------
#define SP 72   /* smem stride halves for pass kernels */
__global__ void __launch_bounds__(256)
attn_pass1(const unsigned char* __restrict__ mask)
{
    __shared__ __half sKh[64*SP], sKl[64*SP];
    const int tid = threadIdx.x, lane = tid & 31, wid = tid >> 5;
    const int bh = blockIdx.y, b = bh >> 4, h = bh & 15;
    const int bq = blockIdx.x * 128;
    const int arow = lane & 15, achk = lane >> 4;
    const int brow = ((lane >> 4) << 3) + (lane & 7), bchk = (lane >> 3) & 1;

    // ---- prologue: Q fragments into registers (two 64-row chunks) ----
    u32 qfh[4][4], qfl[4][4];
    #pragma unroll
    for (int c = 0; c < 2; ++c) {
        #pragma unroll
        for (int i = 0; i < 2; ++i) {
            int e = tid + i * 256;
            int m = e >> 3, ch = e & 7;
            *(uint4*)&sKh[m*SP + ch*8] =
                *(const uint4*)&g_qh_h[(size_t)(b*Ss + bq + c*64 + m)*DM + h*DKh + ch*8];
            *(uint4*)&sKl[m*SP + ch*8] =
                *(const uint4*)&g_qh_l[(size_t)(b*Ss + bq + c*64 + m)*DM + h*DKh + ch*8];
        }
        __syncthreads();
        if ((wid >> 2) == c) {
            int rloc = (wid & 3)*16 + arow;
            #pragma unroll
            for (int kc = 0; kc < 4; ++kc) {
                u32 off = rloc*(SP*2) + (2*kc + achk)*16;
                ldsm4(qfh[kc][0],qfh[kc][1],qfh[kc][2],qfh[kc][3], smaddr(sKh)+off);
                ldsm4(qfl[kc][0],qfl[kc][1],qfl[kc][2],qfl[kc][3], smaddr(sKl)+off);
            }
        }
        __syncthreads();
    }

    const int r0 = bq + wid*16 + (lane >> 2);
    float rs0 = 0.f, rs1 = 0.f;

    for (int kt = 0; kt < 32; ++kt) {
        #pragma unroll
        for (int i = 0; i < 2; ++i) {
            int e = tid + i * 256;
            int m = e >> 3, ch = e & 7;
            *(uint4*)&sKh[m*SP + ch*8] =
                *(const uint4*)&g_kh_h[(size_t)(b*Ss + kt*64 + m)*DM + h*DKh + ch*8];
            *(uint4*)&sKl[m*SP + ch*8] =
                *(const uint4*)&g_kh_l[(size_t)(b*Ss + kt*64 + m)*DM + h*DKh + ch*8];
        }
        __syncthreads();

        float sf[8][4] = {};
        #pragma unroll
        for (int kc = 0; kc < 4; ++kc) {
            #pragma unroll
            for (int ntp = 0; ntp < 4; ++ntp) {
                int row = ntp*16 + brow;
                u32 off = row*(SP*2) + (2*kc + bchk)*16;
                u32 b0,b1,b2,b3, c0,c1,c2,c3;
                ldsm4(b0,b1,b2,b3, smaddr(sKh)+off);
                ldsm4(c0,c1,c2,c3, smaddr(sKl)+off);
                mma16(sf[2*ntp],   qfh[kc], b0, b1);
                mma16(sf[2*ntp],   qfl[kc], b0, b1);
                mma16(sf[2*ntp],   qfh[kc], c0, c1);
                mma16(sf[2*ntp+1], qfh[kc], b2, b3);
                mma16(sf[2*ntp+1], qfl[kc], b2, b3);
                mma16(sf[2*ntp+1], qfh[kc], c2, c3);
            }
        }
        #pragma unroll
        for (int nt = 0; nt < 8; ++nt) {
            int col = kt*64 + nt*8 + (lane & 3)*2;
            u16 m0 = *(const u16*)&mask[((size_t)b*Ss + r0)*Ss + col];
            u16 m1 = *(const u16*)&mask[((size_t)b*Ss + r0 + 8)*Ss + col];
            if (!(m0 & 0x00ff)) rs0 += __expf(sf[nt][0]*0.125f);
            if (!(m0 & 0xff00)) rs0 += __expf(sf[nt][1]*0.125f);
            if (!(m1 & 0x00ff)) rs1 += __expf(sf[nt][2]*0.125f);
            if (!(m1 & 0xff00)) rs1 += __expf(sf[nt][3]*0.125f);
        }
        __syncthreads();
    }

    rs0 += __shfl_xor_sync(0xffffffffu, rs0, 1);
    rs0 += __shfl_xor_sync(0xffffffffu, rs0, 2);
    rs1 += __shfl_xor_sync(0xffffffffu, rs1, 1);
    rs1 += __shfl_xor_sync(0xffffffffu, rs1, 2);
    if ((lane & 3) == 0) {
        g_rinv[(size_t)bh*Ss + r0]     = 1.0f / rs0;
        g_rinv[(size_t)bh*Ss + r0 + 8] = 1.0f / rs1;
    }
}

// ---------------------------------------------------------------------------
// Attention pass 2: recompute S, p = exp(s)*inv, write attn (only write!),
// fuse PV: O += p @ V with S-fragments converted in registers to A-fragments.
// ---------------------------------------------------------------------------
__global__ void __launch_bounds__(256)
attn_pass2(const unsigned char* __restrict__ mask, float* __restrict__ P)
{
    __shared__ __half sKh[64*SP], sKl[64*SP], sVh[64*SP], sVl[64*SP];
    const int tid = threadIdx.x, lane = tid & 31, wid = tid >> 5;
    const int bh = blockIdx.y, b = bh >> 4, h = bh & 15;
    const int bq = blockIdx.x * 128;
    const int arow = lane & 15, achk = lane >> 4;
    const int brow = ((lane >> 4) << 3) + (lane & 7), bchk = (lane >> 3) & 1;

    // Q fragments (via sKh/sKl)
    u32 qfh[4][4], qfl[4][4];
    #pragma unroll
    for (int c = 0; c < 2; ++c) {
        #pragma unroll
        for (int i = 0; i < 2; ++i) {
            int e = tid + i * 256;
            int m = e >> 3, ch = e & 7;
            *(uint4*)&sKh[m*SP + ch*8] =
                *(const uint4*)&g_qh_h[(size_t)(b*Ss + bq + c*64 + m)*DM + h*DKh + ch*8];
            *(uint4*)&sKl[m*SP + ch*8] =
                *(const uint4*)&g_qh_l[(size_t)(b*Ss + bq + c*64 + m)*DM + h*DKh + ch*8];
        }
        __syncthreads();
        if ((wid >> 2) == c) {
            int rloc = (wid & 3)*16 + arow;
            #pragma unroll
            for (int kc = 0; kc < 4; ++kc) {
                u32 off = rloc*(SP*2) + (2*kc + achk)*16;
                ldsm4(qfh[kc][0],qfh[kc][1],qfh[kc][2],qfh[kc][3], smaddr(sKh)+off);
                ldsm4(qfl[kc][0],qfl[kc][1],qfl[kc][2],qfl[kc][3], smaddr(sKl)+off);
            }
        }
        __syncthreads();
    }

    const int r0 = bq + wid*16 + (lane >> 2);
    const float inv0 = g_rinv[(size_t)bh*Ss + r0];
    const float inv1 = g_rinv[(size_t)bh*Ss + r0 + 8];
    float oacc[8][4] = {};

    for (int kt = 0; kt < 32; ++kt) {
        #pragma unroll
        for (int i = 0; i < 2; ++i) {
            int e = tid + i * 256;
            int m = e >> 3, ch = e & 7;
            size_t gk = (size_t)(b*Ss + kt*64 + m)*DM + h*DKh + ch*8;
            *(uint4*)&sKh[m*SP + ch*8] = *(const uint4*)&g_kh_h[gk];
            *(uint4*)&sKl[m*SP + ch*8] = *(const uint4*)&g_kh_l[gk];
            *(uint4*)&sVh[m*SP + ch*8] = *(const uint4*)&g_vh_h[gk];
            *(uint4*)&sVl[m*SP + ch*8] = *(const uint4*)&g_vh_l[gk];
        }
        __syncthreads();

        // S = Q.K^T
        float sf[8][4] = {};
        #pragma unroll
        for (int kc = 0; kc < 4; ++kc) {
            #pragma unroll
            for (int ntp = 0; ntp < 4; ++ntp) {
                int row = ntp*16 + brow;
                u32 off = row*(SP*2) + (2*kc + bchk)*16;
                u32 b0,b1,b2,b3, c0,c1,c2,c3;
                ldsm4(b0,b1,b2,b3, smaddr(sKh)+off);
                ldsm4(c0,c1,c2,c3, smaddr(sKl)+off);
                mma16(sf[2*ntp],   qfh[kc], b0, b1);
                mma16(sf[2*ntp],   qfl[kc], b0, b1);
                mma16(sf[2*ntp],   qfh[kc], c0, c1);
                mma16(sf[2*ntp+1], qfh[kc], b2, b3);
                mma16(sf[2*ntp+1], qfl[kc], b2, b3);
                mma16(sf[2*ntp+1], qfh[kc], c2, c3);
            }
        }

        // p = exp(s)*inv (masked), write final attn
        #pragma unroll
        for (int nt = 0; nt < 8; ++nt) {
            int col = kt*64 + nt*8 + (lane & 3)*2;
            u16 m0 = *(const u16*)&mask[((size_t)b*Ss + r0)*Ss + col];
            u16 m1 = *(const u16*)&mask[((size_t)b*Ss + r0 + 8)*Ss + col];
            float p0 = (m0 & 0x00ff) ? 0.f : __expf(sf[nt][0]*0.125f) * inv0;
            float p1 = (m0 & 0xff00) ? 0.f : __expf(sf[nt][1]*0.125f) * inv0;
            float p2 = (m1 & 0x00ff) ? 0.f : __expf(sf[nt][2]*0.125f) * inv1;
            float p3 = (m1 & 0xff00) ? 0.f : __expf(sf[nt][3]*0.125f) * inv1;
            *(float2*)&P[((size_t)bh*Ss + r0)*Ss + col]     = make_float2(p0, p1);
            *(float2*)&P[((size_t)bh*Ss + r0 + 8)*Ss + col] = make_float2(p2, p3);
            sf[nt][0] = p0; sf[nt][1] = p1; sf[nt][2] = p2; sf[nt][3] = p3;
        }

        // PV: O += p @ V  (A-fragments built in registers from sf)
        #pragma unroll
        for (int kc2 = 0; kc2 < 4; ++kc2) {
            u32 aph[4], apl[4];
            #pragma unroll
            for (int half_ = 0; half_ < 2; ++half_) {
                float* f = sf[2*kc2 + half_];
                __half2 h0 = __floats2half2_rn(f[0], f[1]);
                __half2 h1 = __floats2half2_rn(f[2], f[3]);
                float2 g0 = __half22float2(h0), g1 = __half22float2(h1);
                __half2 l0 = __floats2half2_rn(f[0]-g0.x, f[1]-g0.y);
                __half2 l1 = __floats2half2_rn(f[2]-g1.x, f[3]-g1.y);
                aph[2*half_]   = *(u32*)&h0;  aph[2*half_+1] = *(u32*)&h1;
                apl[2*half_]   = *(u32*)&l0;  apl[2*half_+1] = *(u32*)&l1;
            }
            #pragma unroll
            for (int ntv = 0; ntv < 4; ++ntv) {
                int vrow = kc2*16 + ((lane >> 3) & 1)*8 + (lane & 7);
                int dch  = ntv*16 + (lane >> 4)*8;
                u32 off = vrow*(SP*2) + dch*2;
                u32 b0,b1,b2,b3, c0,c1,c2,c3;
                ldsm4t(b0,b1,b2,b3, smaddr(sVh)+off);
                ldsm4t(c0,c1,c2,c3, smaddr(sVl)+off);
                mma16(oacc[2*ntv],   aph, b0, b1);
                mma16(oacc[2*ntv],   apl, b0, b1);
                mma16(oacc[2*ntv],   aph, c0, c1);
                mma16(oacc[2*ntv+1], aph, b2, b3);
                mma16(oacc[2*ntv+1], apl, b2, b3);
                mma16(oacc[2*ntv+1], aph, c2, c3);
            }
        }
        __syncthreads();
    }

    // write O as fp16 hi/lo (input to out-projection)
    #pragma unroll
    for (int nt = 0; nt < 8; ++nt) {
        int d = nt*8 + (lane & 3)*2;
        size_t i0 = (size_t)(b*Ss + r0)*DM + h*DKh + d;
        size_t i1 = (size_t)(b*Ss + r0 + 8)*DM + h*DKh + d;
        __half2 h0 = __floats2half2_rn(oacc[nt][0], oacc[nt][1]);
        __half2 h1 = __floats2half2_rn(oacc[nt][2], oacc[nt][3]);
        float2 f0 = __half22float2(h0), f1 = __half22float2(h1);
        *(__half2*)&g_oh_h[i0] = h0;
        *(__half2*)&g_oh_h[i1] = h1;
        *(__half2*)&g_oh_l[i0] = __floats2half2_rn(oacc[nt][0]-f0.x, oacc[nt][1]-f0.y);
        *(__half2*)&g_oh_l[i1] = __floats2half2_rn(oacc[nt][2]-f1.x, oacc[nt][3]-f1.y);
    }
}

// ---------------------------------------------------------------------------
// LayerNorm per row of 1024
// ---------------------------------------------------------------------------
__global__ void __launch_bounds__(256)
layernorm(const float* __restrict__ Xin, const float* __restrict__ gamma,
          const float* __restrict__ beta, float* __restrict__ out)
{
    const float* x = Xin + (size_t)blockIdx.x * DM;
    float* o = out + (size_t)blockIdx.x * DM;
    const int tid = threadIdx.x;
    __shared__ float r1[256], r2[256];

    float v[4], s = 0.f, sq = 0.f;
    #pragma unroll
    for (int i = 0; i < 4; ++i) {
        v[i] = x[tid + i * 256];
        s += v[i];
        sq += v[i] * v[i];
    }
    r1[tid] = s; r2[tid] = sq; __syncthreads();
    for (int st = 128; st > 0; st >>= 1) {
        if (tid < st) { r1[tid] += r1[tid + st]; r2[tid] += r2[tid + st]; }
        __syncthreads();
    }
    float mean = r1[0] * (1.0f / DM);
    float var  = r2[0] * (1.0f / DM) - mean * mean;
    float inv = rsqrtf(var + 1e-5f);
    #pragma unroll
    for (int i = 0; i < 4; ++i) {
        int c = tid + i * 256;
        o[c] = (v[i] - mean) * inv * gamma[c] + beta[c];
    }
}

// ---------------------------------------------------------------------------
extern "C" void kernel_launch(void* const* d_in, const int* in_sizes, int n_in,
                              void* d_out, int out_size)
{
    const float* q    = (const float*)d_in[0];
    const float* k    = (const float*)d_in[1];
    const float* v    = (const float*)d_in[2];
    const unsigned char* mask = (const unsigned char*)d_in[3];
    const float* Wq   = (const float*)d_in[4];
    const float* bq   = (const float*)d_in[5];
    const float* Wk   = (const float*)d_in[6];
    const float* bk   = (const float*)d_in[7];
    const float* Wv   = (const float*)d_in[8];
    const float* bv   = (const float*)d_in[9];
    const float* Wo   = (const float*)d_in[10];
    const float* bo   = (const float*)d_in[11];
    const float* ln_g = (const float*)d_in[12];
    const float* ln_b = (const float*)d_in[13];

    float* outp = (float*)d_out;
    float* attn = outp + OUT_ELEMS;

    __half *qi_h,*qi_l,*ki_h,*ki_l,*vi_h,*vi_l;
    __half *wq_h,*wq_l,*wk_h,*wk_l,*wv_h,*wv_l,*wo_h,*wo_l;
    __half *qh_h,*qh_l,*kh_h,*kh_l,*vh_h,*vh_l,*oh_h,*oh_l;
    float *y;
    cudaGetSymbolAddress((void**)&qi_h, g_qi_h); cudaGetSymbolAddress((void**)&qi_l, g_qi_l);
    cudaGetSymbolAddress((void**)&ki_h, g_ki_h); cudaGetSymbolAddress((void**)&ki_l, g_ki_l);
    cudaGetSymbolAddress((void**)&vi_h, g_vi_h); cudaGetSymbolAddress((void**)&vi_l, g_vi_l);
    cudaGetSymbolAddress((void**)&wq_h, g_wq_h); cudaGetSymbolAddress((void**)&wq_l, g_wq_l);
    cudaGetSymbolAddress((void**)&wk_h, g_wk_h); cudaGetSymbolAddress((void**)&wk_l, g_wk_l);
    cudaGetSymbolAddress((void**)&wv_h, g_wv_h); cudaGetSymbolAddress((void**)&wv_l, g_wv_l);
    cudaGetSymbolAddress((void**)&wo_h, g_wo_h); cudaGetSymbolAddress((void**)&wo_l, g_wo_l);
    cudaGetSymbolAddress((void**)&qh_h, g_qh_h); cudaGetSymbolAddress((void**)&qh_l, g_qh_l);
    cudaGetSymbolAddress((void**)&kh_h, g_kh_h); cudaGetSymbolAddress((void**)&kh_l, g_kh_l);
    cudaGetSymbolAddress((void**)&vh_h, g_vh_h); cudaGetSymbolAddress((void**)&vh_l, g_vh_l);
    cudaGetSymbolAddress((void**)&oh_h, g_oh_h); cudaGetSymbolAddress((void**)&oh_l, g_oh_l);
    cudaGetSymbolAddress((void**)&y, g_y);

    const int n4 = MTOK * DM / 4;
    split_f32<<<(n4+255)/256, 256>>>(q, qi_h, qi_l, n4);
    split_f32<<<(n4+255)/256, 256>>>(k, ki_h, ki_l, n4);
    split_f32<<<(n4+255)/256, 256>>>(v, vi_h, vi_l, n4);

    dim3 gT(DM/32, DM/32), bT(32, 8);
    splitT_w<<<gT, bT>>>(Wq, wq_h, wq_l);
    splitT_w<<<gT, bT>>>(Wk, wk_h, wk_l);
    splitT_w<<<gT, bT>>>(Wv, wv_h, wv_l);
    splitT_w<<<gT, bT>>>(Wo, wo_h, wo_l);

    dim3 gProj(DM/128, MTOK/128);   // (8, 32)
    gemm_h3<<<gProj, 256>>>(qi_h, qi_l, wq_h, wq_l, bq, nullptr,
                            qh_h, qh_l, nullptr, MTOK, DM, DM);
    gemm_h3<<<gProj, 256>>>(ki_h, ki_l, wk_h, wk_l, bk, nullptr,
                            kh_h, kh_l, nullptr, MTOK, DM, DM);
    gemm_h3<<<gProj, 256>>>(vi_h, vi_l, wv_h, wv_l, bv, nullptr,
                            vh_h, vh_l, nullptr, MTOK, DM, DM);

    dim3 gAttn(Ss/128, Bb*Hh);      // (16, 32)
    attn_pass1<<<gAttn, 256>>>(mask);
    attn_pass2<<<gAttn, 256>>>(mask, attn);

    gemm_h3<<<gProj, 256>>>(oh_h, oh_l, wo_h, wo_l, bo, q,
                            nullptr, nullptr, y, MTOK, DM, DM);

    layernorm<<<MTOK, 256>>>(y, ln_g, ln_b, outp);
}

// round 6
// speedup vs baseline: 2.3915x; 1.0974x over previous
#include <cuda_runtime.h>
#include <cuda_fp16.h>
#include <math.h>

// Problem constants
#define Bb 2
#define Ss 2048
#define DM 1024
#define Hh 16
#define DKh 64
#define MTOK (Bb*Ss)                 // 4096
#define NROWS (Bb*Hh*Ss)             // 65536
#define OUT_ELEMS ((size_t)Bb*Ss*DM)

#define SCALE_L2E 0.18033688011112042f   // 0.125 * log2(e)

typedef unsigned int u32;
typedef unsigned short u16;

// ---------------- device scratch ----------------
__device__ __half g_qi_h[MTOK*DM], g_qi_l[MTOK*DM];
__device__ __half g_ki_h[MTOK*DM], g_ki_l[MTOK*DM];
__device__ __half g_vi_h[MTOK*DM], g_vi_l[MTOK*DM];
__device__ __half g_wq_h[DM*DM], g_wq_l[DM*DM];
__device__ __half g_wk_h[DM*DM], g_wk_l[DM*DM];
__device__ __half g_wv_h[DM*DM], g_wv_l[DM*DM];
__device__ __half g_wo_h[DM*DM], g_wo_l[DM*DM];
__device__ __half g_qh_h[MTOK*DM], g_qh_l[MTOK*DM];
__device__ __half g_kh_h[MTOK*DM], g_kh_l[MTOK*DM];
__device__ __half g_vh_h[MTOK*DM], g_vh_l[MTOK*DM];
__device__ __half g_oh_h[MTOK*DM], g_oh_l[MTOK*DM];
__device__ float  g_y[MTOK*DM];
__device__ float  g_rinv[NROWS];

// ---------------- helpers ----------------
__device__ __forceinline__ u32 smaddr(const void* p) {
    return (u32)__cvta_generic_to_shared(p);
}
__device__ __forceinline__ void ldsm4(u32& r0, u32& r1, u32& r2, u32& r3, u32 a) {
    asm volatile("ldmatrix.sync.aligned.m8n8.x4.shared.b16 {%0,%1,%2,%3},[%4];"
                 : "=r"(r0), "=r"(r1), "=r"(r2), "=r"(r3) : "r"(a));
}
__device__ __forceinline__ void ldsm4t(u32& r0, u32& r1, u32& r2, u32& r3, u32 a) {
    asm volatile("ldmatrix.sync.aligned.m8n8.x4.trans.shared.b16 {%0,%1,%2,%3},[%4];"
                 : "=r"(r0), "=r"(r1), "=r"(r2), "=r"(r3) : "r"(a));
}
__device__ __forceinline__ void mma16(float* d, const u32* a, u32 b0, u32 b1) {
    asm volatile(
        "mma.sync.aligned.m16n8k16.row.col.f32.f16.f16.f32 "
        "{%0,%1,%2,%3},{%4,%5,%6,%7},{%8,%9},{%0,%1,%2,%3};"
        : "+f"(d[0]), "+f"(d[1]), "+f"(d[2]), "+f"(d[3])
        : "r"(a[0]), "r"(a[1]), "r"(a[2]), "r"(a[3]), "r"(b0), "r"(b1));
}
__device__ __forceinline__ void cpa16(u32 dst, const void* src) {
    asm volatile("cp.async.cg.shared.global [%0], [%1], 16;" :: "r"(dst), "l"(src));
}
#define CP_COMMIT() asm volatile("cp.async.commit_group;")
#define CP_WAIT1()  asm volatile("cp.async.wait_group 1;")
#define CP_WAIT0()  asm volatile("cp.async.wait_group 0;")
__device__ __forceinline__ float ex2f(float x) {
    float r; asm("ex2.approx.f32 %0, %1;" : "=f"(r) : "f"(x)); return r;
}

// ---------------- split kernels ----------------
__global__ void __launch_bounds__(256)
split_f32(const float* __restrict__ src, __half* __restrict__ dh,
          __half* __restrict__ dl, int n4)
{
    int i = blockIdx.x * 256 + threadIdx.x;
    if (i >= n4) return;
    float4 v = ((const float4*)src)[i];
    __half2 h0 = __floats2half2_rn(v.x, v.y);
    __half2 h1 = __floats2half2_rn(v.z, v.w);
    float2 f0 = __half22float2(h0), f1 = __half22float2(h1);
    ((__half2*)dh)[2*i]   = h0; ((__half2*)dh)[2*i+1] = h1;
    ((__half2*)dl)[2*i]   = __floats2half2_rn(v.x - f0.x, v.y - f0.y);
    ((__half2*)dl)[2*i+1] = __floats2half2_rn(v.z - f1.x, v.w - f1.y);
}

// W[K][N] -> T[N][K] split hi/lo
__global__ void __launch_bounds__(256)
splitT_w(const float* __restrict__ W, __half* __restrict__ th,
         __half* __restrict__ tl)
{
    __shared__ float t[32][33];
    int kb = blockIdx.y * 32, nb = blockIdx.x * 32;
    int tx = threadIdx.x, ty = threadIdx.y;
    #pragma unroll
    for (int i = 0; i < 4; ++i)
        t[ty + i*8][tx] = W[(size_t)(kb + ty + i*8) * DM + nb + tx];
    __syncthreads();
    #pragma unroll
    for (int i = 0; i < 4; ++i) {
        int n = nb + ty + i*8, k = kb + tx;
        float v = t[tx][ty + i*8];
        __half h = __float2half_rn(v);
        th[(size_t)n * DM + k] = h;
        tl[(size_t)n * DM + k] = __float2half_rn(v - __half2float(h));
    }
}

// ---------------------------------------------------------------------------
// fp16 3-term GEMM, cp.async double-buffered.
// C = ((Ah+Al)(Bh+Bl)^T + bias) * omul  (+R when Cf)
// ---------------------------------------------------------------------------
#define SG 40
#define GARR (128*SG)        // halves per array
#define GSTG (4*GARR)        // halves per stage
__global__ void __launch_bounds__(256)
gemm_h3(const __half* __restrict__ Ah, const __half* __restrict__ Al,
        const __half* __restrict__ Bh, const __half* __restrict__ Bl,
        const float* __restrict__ bias, const float* __restrict__ R,
        float omul,
        __half* __restrict__ Ch, __half* __restrict__ Cl,
        float* __restrict__ Cf, int M, int N, int K)
{
    extern __shared__ __half dsm[];
    const int tid = threadIdx.x, lane = tid & 31, wid = tid >> 5;
    const int wm = wid & 3, wn = wid >> 2;
    const int bm = blockIdx.y * 128, bn = blockIdx.x * 128;
    float acc[2][8][4] = {};
    const int arow = lane & 15, achk = lane >> 4;
    const int brow = ((lane >> 4) << 3) + (lane & 7), bchk = (lane >> 3) & 1;
    const u32 smbase = smaddr(dsm);

    auto load_stage = [&](int st, int k0) {
        u32 base = smbase + (u32)st * GSTG * 2;
        #pragma unroll
        for (int i = 0; i < 2; ++i) {
            int e = tid + i * 256;
            int m = e >> 2, c = e & 3;
            size_t ga = (size_t)(bm + m) * K + k0 + c*8;
            size_t gb = (size_t)(bn + m) * K + k0 + c*8;
            u32 o = (u32)(m*SG + c*8) * 2;
            cpa16(base + 0*GARR*2 + o, Ah + ga);
            cpa16(base + 1*GARR*2 + o, Al + ga);
            cpa16(base + 2*GARR*2 + o, Bh + gb);
            cpa16(base + 3*GARR*2 + o, Bl + gb);
        }
        CP_COMMIT();
    };

    const int nk = K / 32;
    load_stage(0, 0);
    for (int kt = 0; kt < nk; ++kt) {
        if (kt + 1 < nk) { load_stage((kt+1)&1, (kt+1)*32); CP_WAIT1(); }
        else             { CP_WAIT0(); }
        __syncthreads();
        const u32 sAh = smbase + (u32)(kt&1)*GSTG*2;
        const u32 sAl = sAh + GARR*2;
        const u32 sBh = sAl + GARR*2;
        const u32 sBl = sBh + GARR*2;
        #pragma unroll
        for (int kc = 0; kc < 2; ++kc) {
            u32 ah[2][4], al[2][4];
            #pragma unroll
            for (int mt = 0; mt < 2; ++mt) {
                int row = wm*32 + mt*16 + arow;
                u32 off = row*(SG*2) + (2*kc + achk)*16;
                ldsm4(ah[mt][0],ah[mt][1],ah[mt][2],ah[mt][3], sAh+off);
                ldsm4(al[mt][0],al[mt][1],al[mt][2],al[mt][3], sAl+off);
            }
            #pragma unroll
            for (int ntp = 0; ntp < 4; ++ntp) {
                int row = wn*64 + ntp*16 + brow;
                u32 off = row*(SG*2) + (2*kc + bchk)*16;
                u32 b0,b1,b2,b3, c0,c1,c2,c3;
                ldsm4(b0,b1,b2,b3, sBh+off);
                ldsm4(c0,c1,c2,c3, sBl+off);
                #pragma unroll
                for (int mt = 0; mt < 2; ++mt) {
                    mma16(acc[mt][2*ntp],   ah[mt], b0, b1);
                    mma16(acc[mt][2*ntp],   al[mt], b0, b1);
                    mma16(acc[mt][2*ntp],   ah[mt], c0, c1);
                    mma16(acc[mt][2*ntp+1], ah[mt], b2, b3);
                    mma16(acc[mt][2*ntp+1], al[mt], b2, b3);
                    mma16(acc[mt][2*ntp+1], ah[mt], c2, c3);
                }
            }
        }
        __syncthreads();
    }

    #pragma unroll
    for (int mt = 0; mt < 2; ++mt) {
        int r0 = bm + wm*32 + mt*16 + (lane >> 2);
        #pragma unroll
        for (int nt = 0; nt < 8; ++nt) {
            int n = bn + wn*64 + nt*8 + (lane & 3)*2;
            float2 bs = *(const float2*)&bias[n];
            float* d = acc[mt][nt];
            float v00 = (d[0]+bs.x)*omul, v01 = (d[1]+bs.y)*omul;
            float v10 = (d[2]+bs.x)*omul, v11 = (d[3]+bs.y)*omul;
            if (Cf) {
                float2 ra = *(const float2*)&R[(size_t)r0*N + n];
                float2 rb = *(const float2*)&R[(size_t)(r0+8)*N + n];
                *(float2*)&Cf[(size_t)r0*N + n]     = make_float2(v00+ra.x, v01+ra.y);
                *(float2*)&Cf[(size_t)(r0+8)*N + n] = make_float2(v10+rb.x, v11+rb.y);
            } else {
                __half2 h0 = __floats2half2_rn(v00, v01);
                __half2 h1 = __floats2half2_rn(v10, v11);
                float2 f0 = __half22float2(h0), f1 = __half22float2(h1);
                *(__half2*)&Ch[(size_t)r0*N + n]     = h0;
                *(__half2*)&Ch[(size_t)(r0+8)*N + n] = h1;
                *(__half2*)&Cl[(size_t)r0*N + n]     = __floats2half2_rn(v00-f0.x, v01-f0.y);
                *(__half2*)&Cl[(size_t)(r0+8)*N + n] = __floats2half2_rn(v10-f1.x, v11-f1.y);
            }
        }
    }
}

// ---------------------------------------------------------------------------
// Pass 1: row sums of 2^(Q'.K^T) (masked); Q' pre-scaled by 0.125*log2e.
// Static double-buffered K tiles.
// ---------------------------------------------------------------------------
#define SP 72
__global__ void __launch_bounds__(256)
attn_pass1(const unsigned char* __restrict__ mask)
{
    __shared__ __half sK[2][2][64*SP];   // [stage][h/l]
    const int tid = threadIdx.x, lane = tid & 31, wid = tid >> 5;
    const int bh = blockIdx.y, b = bh >> 4, h = bh & 15;
    const int bq = blockIdx.x * 128;
    const int arow = lane & 15, achk = lane >> 4;
    const int brow = ((lane >> 4) << 3) + (lane & 7), bchk = (lane >> 3) & 1;

    // Q fragments
    u32 qfh[4][4], qfl[4][4];
    #pragma unroll
    for (int c = 0; c < 2; ++c) {
        #pragma unroll
        for (int i = 0; i < 2; ++i) {
            int e = tid + i * 256;
            int m = e >> 3, ch = e & 7;
            size_t gq = (size_t)(b*Ss + bq + c*64 + m)*DM + h*DKh + ch*8;
            *(uint4*)&sK[0][0][m*SP + ch*8] = *(const uint4*)&g_qh_h[gq];
            *(uint4*)&sK[0][1][m*SP + ch*8] = *(const uint4*)&g_qh_l[gq];
        }
        __syncthreads();
        if ((wid >> 2) == c) {
            int rloc = (wid & 3)*16 + arow;
            #pragma unroll
            for (int kc = 0; kc < 4; ++kc) {
                u32 off = rloc*(SP*2) + (2*kc + achk)*16;
                ldsm4(qfh[kc][0],qfh[kc][1],qfh[kc][2],qfh[kc][3], smaddr(sK[0][0])+off);
                ldsm4(qfl[kc][0],qfl[kc][1],qfl[kc][2],qfl[kc][3], smaddr(sK[0][1])+off);
            }
        }
        __syncthreads();
    }

    auto load_stage = [&](int st, int kt) {
        #pragma unroll
        for (int i = 0; i < 2; ++i) {
            int e = tid + i * 256;
            int m = e >> 3, ch = e & 7;
            size_t gk = (size_t)(b*Ss + kt*64 + m)*DM + h*DKh + ch*8;
            u32 o = (u32)(m*SP + ch*8)*2;
            cpa16(smaddr(sK[st][0]) + o, g_kh_h + gk);
            cpa16(smaddr(sK[st][1]) + o, g_kh_l + gk);
        }
        CP_COMMIT();
    };

    const int r0 = bq + wid*16 + (lane >> 2);
    float rs0 = 0.f, rs1 = 0.f;

    load_stage(0, 0);
    for (int kt = 0; kt < 32; ++kt) {
        if (kt + 1 < 32) { load_stage((kt+1)&1, kt+1); CP_WAIT1(); }
        else             { CP_WAIT0(); }
        __syncthreads();
        const u32 sKh = smaddr(sK[kt&1][0]);
        const u32 sKl = smaddr(sK[kt&1][1]);

        float sf[8][4] = {};
        #pragma unroll
        for (int kc = 0; kc < 4; ++kc) {
            #pragma unroll
            for (int ntp = 0; ntp < 4; ++ntp) {
                int row = ntp*16 + brow;
                u32 off = row*(SP*2) + (2*kc + bchk)*16;
                u32 b0,b1,b2,b3, c0,c1,c2,c3;
                ldsm4(b0,b1,b2,b3, sKh+off);
                ldsm4(c0,c1,c2,c3, sKl+off);
                mma16(sf[2*ntp],   qfh[kc], b0, b1);
                mma16(sf[2*ntp],   qfl[kc], b0, b1);
                mma16(sf[2*ntp],   qfh[kc], c0, c1);
                mma16(sf[2*ntp+1], qfh[kc], b2, b3);
                mma16(sf[2*ntp+1], qfl[kc], b2, b3);
                mma16(sf[2*ntp+1], qfh[kc], c2, c3);
            }
        }
        #pragma unroll
        for (int nt = 0; nt < 8; ++nt) {
            int col = kt*64 + nt*8 + (lane & 3)*2;
            u16 m0 = *(const u16*)&mask[((size_t)b*Ss + r0)*Ss + col];
            u16 m1 = *(const u16*)&mask[((size_t)b*Ss + r0 + 8)*Ss + col];
            if (!(m0 & 0x00ff)) rs0 += ex2f(sf[nt][0]);
            if (!(m0 & 0xff00)) rs0 += ex2f(sf[nt][1]);
            if (!(m1 & 0x00ff)) rs1 += ex2f(sf[nt][2]);
            if (!(m1 & 0xff00)) rs1 += ex2f(sf[nt][3]);
        }
        __syncthreads();
    }

    rs0 += __shfl_xor_sync(0xffffffffu, rs0, 1);
    rs0 += __shfl_xor_sync(0xffffffffu, rs0, 2);
    rs1 += __shfl_xor_sync(0xffffffffu, rs1, 1);
    rs1 += __shfl_xor_sync(0xffffffffu, rs1, 2);
    if ((lane & 3) == 0) {
        g_rinv[(size_t)bh*Ss + r0]     = 1.0f / rs0;
        g_rinv[(size_t)bh*Ss + r0 + 8] = 1.0f / rs1;
    }
}

// ---------------------------------------------------------------------------
// Pass 2: recompute S, p = 2^s * inv -> write attn; PV fused (p rounded to
// fp16, V 2-term). cp.async double-buffered K+V (dynamic smem).
// ---------------------------------------------------------------------------
#define PARR (64*SP)        // halves per array
#define PSTG (4*PARR)       // halves per stage
__global__ void __launch_bounds__(256)
attn_pass2(const unsigned char* __restrict__ mask, float* __restrict__ P)
{
    extern __shared__ __half dsm[];
    const int tid = threadIdx.x, lane = tid & 31, wid = tid >> 5;
    const int bh = blockIdx.y, b = bh >> 4, h = bh & 15;
    const int bq = blockIdx.x * 128;
    const int arow = lane & 15, achk = lane >> 4;
    const int brow = ((lane >> 4) << 3) + (lane & 7), bchk = (lane >> 3) & 1;
    const u32 smbase = smaddr(dsm);

    // Q fragments via stage-0 buffers
    u32 qfh[4][4], qfl[4][4];
    #pragma unroll
    for (int c = 0; c < 2; ++c) {
        #pragma unroll
        for (int i = 0; i < 2; ++i) {
            int e = tid + i * 256;
            int m = e >> 3, ch = e & 7;
            size_t gq = (size_t)(b*Ss + bq + c*64 + m)*DM + h*DKh + ch*8;
            *(uint4*)&dsm[m*SP + ch*8]        = *(const uint4*)&g_qh_h[gq];
            *(uint4*)&dsm[PARR + m*SP + ch*8] = *(const uint4*)&g_qh_l[gq];
        }
        __syncthreads();
        if ((wid >> 2) == c) {
            int rloc = (wid & 3)*16 + arow;
            #pragma unroll
            for (int kc = 0; kc < 4; ++kc) {
                u32 off = rloc*(SP*2) + (2*kc + achk)*16;
                ldsm4(qfh[kc][0],qfh[kc][1],qfh[kc][2],qfh[kc][3], smbase+off);
                ldsm4(qfl[kc][0],qfl[kc][1],qfl[kc][2],qfl[kc][3], smbase+PARR*2+off);
            }
        }
        __syncthreads();
    }

    auto load_stage = [&](int st, int kt) {
        u32 base = smbase + (u32)st * PSTG * 2;
        #pragma unroll
        for (int i = 0; i < 2; ++i) {
            int e = tid + i * 256;
            int m = e >> 3, ch = e & 7;
            size_t gk = (size_t)(b*Ss + kt*64 + m)*DM + h*DKh + ch*8;
            u32 o = (u32)(m*SP + ch*8)*2;
            cpa16(base + 0*PARR*2 + o, g_kh_h + gk);
            cpa16(base + 1*PARR*2 + o, g_kh_l + gk);
            cpa16(base + 2*PARR*2 + o, g_vh_h + gk);
            cpa16(base + 3*PARR*2 + o, g_vh_l + gk);
        }
        CP_COMMIT();
    };

    const int r0 = bq + wid*16 + (lane >> 2);
    const float inv0 = g_rinv[(size_t)bh*Ss + r0];
    const float inv1 = g_rinv[(size_t)bh*Ss + r0 + 8];
    float oacc[8][4] = {};

    load_stage(0, 0);
    for (int kt = 0; kt < 32; ++kt) {
        if (kt + 1 < 32) { load_stage((kt+1)&1, kt+1); CP_WAIT1(); }
        else             { CP_WAIT0(); }
        __syncthreads();
        const u32 sKh = smbase + (u32)(kt&1)*PSTG*2;
        const u32 sKl = sKh + PARR*2;
        const u32 sVh = sKl + PARR*2;
        const u32 sVl = sVh + PARR*2;

        // S = Q'.K^T (3-term)
        float sf[8][4] = {};
        #pragma unroll
        for (int kc = 0; kc < 4; ++kc) {
            #pragma unroll
            for (int ntp = 0; ntp < 4; ++ntp) {
                int row = ntp*16 + brow;
                u32 off = row*(SP*2) + (2*kc + bchk)*16;
                u32 b0,b1,b2,b3, c0,c1,c2,c3;
                ldsm4(b0,b1,b2,b3, sKh+off);
                ldsm4(c0,c1,c2,c3, sKl+off);
                mma16(sf[2*ntp],   qfh[kc], b0, b1);
                mma16(sf[2*ntp],   qfl[kc], b0, b1);
                mma16(sf[2*ntp],   qfh[kc], c0, c1);
                mma16(sf[2*ntp+1], qfh[kc], b2, b3);
                mma16(sf[2*ntp+1], qfl[kc], b2, b3);
                mma16(sf[2*ntp+1], qfh[kc], c2, c3);
            }
        }

        // p = 2^s * inv (masked), write final attn
        #pragma unroll
        for (int nt = 0; nt < 8; ++nt) {
            int col = kt*64 + nt*8 + (lane & 3)*2;
            u16 m0 = *(const u16*)&mask[((size_t)b*Ss + r0)*Ss + col];
            u16 m1 = *(const u16*)&mask[((size_t)b*Ss + r0 + 8)*Ss + col];
            float p0 = (m0 & 0x00ff) ? 0.f : ex2f(sf[nt][0]) * inv0;
            float p1 = (m0 & 0xff00) ? 0.f : ex2f(sf[nt][1]) * inv0;
            float p2 = (m1 & 0x00ff) ? 0.f : ex2f(sf[nt][2]) * inv1;
            float p3 = (m1 & 0xff00) ? 0.f : ex2f(sf[nt][3]) * inv1;
            *(float2*)&P[((size_t)bh*Ss + r0)*Ss + col]     = make_float2(p0, p1);
            *(float2*)&P[((size_t)bh*Ss + r0 + 8)*Ss + col] = make_float2(p2, p3);
            sf[nt][0] = p0; sf[nt][1] = p1; sf[nt][2] = p2; sf[nt][3] = p3;
        }

        // PV: O += p16 @ (Vh + Vl)
        #pragma unroll
        for (int kc2 = 0; kc2 < 4; ++kc2) {
            u32 aph[4];
            #pragma unroll
            for (int half_ = 0; half_ < 2; ++half_) {
                float* f = sf[2*kc2 + half_];
                __half2 h0 = __floats2half2_rn(f[0], f[1]);
                __half2 h1 = __floats2half2_rn(f[2], f[3]);
                aph[2*half_]   = *(u32*)&h0;
                aph[2*half_+1] = *(u32*)&h1;
            }
            #pragma unroll
            for (int ntv = 0; ntv < 4; ++ntv) {
                int vrow = kc2*16 + ((lane >> 3) & 1)*8 + (lane & 7);
                int dch  = ntv*16 + (lane >> 4)*8;
                u32 off = vrow*(SP*2) + dch*2;
                u32 b0,b1,b2,b3, c0,c1,c2,c3;
                ldsm4t(b0,b1,b2,b3, sVh+off);
                ldsm4t(c0,c1,c2,c3, sVl+off);
                mma16(oacc[2*ntv],   aph, b0, b1);
                mma16(oacc[2*ntv],   aph, c0, c1);
                mma16(oacc[2*ntv+1], aph, b2, b3);
                mma16(oacc[2*ntv+1], aph, c2, c3);
            }
        }
        __syncthreads();
    }

    #pragma unroll
    for (int nt = 0; nt < 8; ++nt) {
        int d = nt*8 + (lane & 3)*2;
        size_t i0 = (size_t)(b*Ss + r0)*DM + h*DKh + d;
        size_t i1 = (size_t)(b*Ss + r0 + 8)*DM + h*DKh + d;
        __half2 h0 = __floats2half2_rn(oacc[nt][0], oacc[nt][1]);
        __half2 h1 = __floats2half2_rn(oacc[nt][2], oacc[nt][3]);
        float2 f0 = __half22float2(h0), f1 = __half22float2(h1);
        *(__half2*)&g_oh_h[i0] = h0;
        *(__half2*)&g_oh_h[i1] = h1;
        *(__half2*)&g_oh_l[i0] = __floats2half2_rn(oacc[nt][0]-f0.x, oacc[nt][1]-f0.y);
        *(__half2*)&g_oh_l[i1] = __floats2half2_rn(oacc[nt][2]-f1.x, oacc[nt][3]-f1.y);
    }
}

// ---------------------------------------------------------------------------
// LayerNorm per row of 1024
// ---------------------------------------------------------------------------
__global__ void __launch_bounds__(256)
layernorm(const float* __restrict__ Xin, const float* __restrict__ gamma,
          const float* __restrict__ beta, float* __restrict__ out)
{
    const float* x = Xin + (size_t)blockIdx.x * DM;
    float* o = out + (size_t)blockIdx.x * DM;
    const int tid = threadIdx.x;
    __shared__ float r1[256], r2[256];

    float v[4], s = 0.f, sq = 0.f;
    #pragma unroll
    for (int i = 0; i < 4; ++i) {
        v[i] = x[tid + i * 256];
        s += v[i];
        sq += v[i] * v[i];
    }
    r1[tid] = s; r2[tid] = sq; __syncthreads();
    for (int st = 128; st > 0; st >>= 1) {
        if (tid < st) { r1[tid] += r1[tid + st]; r2[tid] += r2[tid + st]; }
        __syncthreads();
    }
    float mean = r1[0] * (1.0f / DM);
    float var  = r2[0] * (1.0f / DM) - mean * mean;
    float inv = rsqrtf(var + 1e-5f);
    #pragma unroll
    for (int i = 0; i < 4; ++i) {
        int c = tid + i * 256;
        o[c] = (v[i] - mean) * inv * gamma[c] + beta[c];
    }
}

// ---------------------------------------------------------------------------
extern "C" void kernel_launch(void* const* d_in, const int* in_sizes, int n_in,
                              void* d_out, int out_size)
{
    const float* q    = (const float*)d_in[0];
    const float* k    = (const float*)d_in[1];
    const float* v    = (const float*)d_in[2];
    const unsigned char* mask = (const unsigned char*)d_in[3];
    const float* Wq   = (const float*)d_in[4];
    const float* bq   = (const float*)d_in[5];
    const float* Wk   = (const float*)d_in[6];
    const float* bk   = (const float*)d_in[7];
    const float* Wv   = (const float*)d_in[8];
    const float* bv   = (const float*)d_in[9];
    const float* Wo   = (const float*)d_in[10];
    const float* bo   = (const float*)d_in[11];
    const float* ln_g = (const float*)d_in[12];
    const float* ln_b = (const float*)d_in[13];

    float* outp = (float*)d_out;
    float* attn = outp + OUT_ELEMS;

    __half *qi_h,*qi_l,*ki_h,*ki_l,*vi_h,*vi_l;
    __half *wq_h,*wq_l,*wk_h,*wk_l,*wv_h,*wv_l,*wo_h,*wo_l;
    __half *qh_h,*qh_l,*kh_h,*kh_l,*vh_h,*vh_l,*oh_h,*oh_l;
    float *y;
    cudaGetSymbolAddress((void**)&qi_h, g_qi_h); cudaGetSymbolAddress((void**)&qi_l, g_qi_l);
    cudaGetSymbolAddress((void**)&ki_h, g_ki_h); cudaGetSymbolAddress((void**)&ki_l, g_ki_l);
    cudaGetSymbolAddress((void**)&vi_h, g_vi_h); cudaGetSymbolAddress((void**)&vi_l, g_vi_l);
    cudaGetSymbolAddress((void**)&wq_h, g_wq_h); cudaGetSymbolAddress((void**)&wq_l, g_wq_l);
    cudaGetSymbolAddress((void**)&wk_h, g_wk_h); cudaGetSymbolAddress((void**)&wk_l, g_wk_l);
    cudaGetSymbolAddress((void**)&wv_h, g_wv_h); cudaGetSymbolAddress((void**)&wv_l, g_wv_l);
    cudaGetSymbolAddress((void**)&wo_h, g_wo_h); cudaGetSymbolAddress((void**)&wo_l, g_wo_l);
    cudaGetSymbolAddress((void**)&qh_h, g_qh_h); cudaGetSymbolAddress((void**)&qh_l, g_qh_l);
    cudaGetSymbolAddress((void**)&kh_h, g_kh_h); cudaGetSymbolAddress((void**)&kh_l, g_kh_l);
    cudaGetSymbolAddress((void**)&vh_h, g_vh_h); cudaGetSymbolAddress((void**)&vh_l, g_vh_l);
    cudaGetSymbolAddress((void**)&oh_h, g_oh_h); cudaGetSymbolAddress((void**)&oh_l, g_oh_l);
    cudaGetSymbolAddress((void**)&y, g_y);

    static bool attr_done = false;
    const int GEMM_SMEM = 2 * GSTG * 2;   // 163840? no: 2 stages * 4*128*40 halves * 2B = 81920
    const int P2_SMEM   = 2 * PSTG * 2;   // 2 stages * 4*64*72 halves * 2B = 73728
    if (!attr_done) {
        cudaFuncSetAttribute(gemm_h3,   cudaFuncAttributeMaxDynamicSharedMemorySize, GEMM_SMEM);
        cudaFuncSetAttribute(attn_pass2, cudaFuncAttributeMaxDynamicSharedMemorySize, P2_SMEM);
        attr_done = true;
    }

    const int n4 = MTOK * DM / 4;
    split_f32<<<(n4+255)/256, 256>>>(q, qi_h, qi_l, n4);
    split_f32<<<(n4+255)/256, 256>>>(k, ki_h, ki_l, n4);
    split_f32<<<(n4+255)/256, 256>>>(v, vi_h, vi_l, n4);

    dim3 gT(DM/32, DM/32), bT(32, 8);
    splitT_w<<<gT, bT>>>(Wq, wq_h, wq_l);
    splitT_w<<<gT, bT>>>(Wk, wk_h, wk_l);
    splitT_w<<<gT, bT>>>(Wv, wv_h, wv_l);
    splitT_w<<<gT, bT>>>(Wo, wo_h, wo_l);

    dim3 gProj(DM/128, MTOK/128);   // (8, 32)
    gemm_h3<<<gProj, 256, GEMM_SMEM>>>(qi_h, qi_l, wq_h, wq_l, bq, nullptr,
                                       SCALE_L2E, qh_h, qh_l, nullptr, MTOK, DM, DM);
    gemm_h3<<<gProj, 256, GEMM_SMEM>>>(ki_h, ki_l, wk_h, wk_l, bk, nullptr,
                                       1.0f, kh_h, kh_l, nullptr, MTOK, DM, DM);
    gemm_h3<<<gProj, 256, GEMM_SMEM>>>(vi_h, vi_l, wv_h, wv_l, bv, nullptr,
                                       1.0f, vh_h, vh_l, nullptr, MTOK, DM, DM);

    dim3 gAttn(Ss/128, Bb*Hh);      // (16, 32)
    attn_pass1<<<gAttn, 256>>>(mask);
    attn_pass2<<<gAttn, 256, P2_SMEM>>>(mask, attn);

    gemm_h3<<<gProj, 256, GEMM_SMEM>>>(oh_h, oh_l, wo_h, wo_l, bo, q,
                                       1.0f, nullptr, nullptr, y, MTOK, DM, DM);

    layernorm<<<MTOK, 256>>>(y, ln_g, ln_b, outp);
}

// round 7
// speedup vs baseline: 2.9939x; 1.2519x over previous
#include <cuda_runtime.h>
#include <cuda_fp16.h>
#include <math.h>

// Problem constants
#define Bb 2
#define Ss 2048
#define DM 1024
#define Hh 16
#define DKh 64
#define MTOK (Bb*Ss)                 // 4096
#define NROWS (Bb*Hh*Ss)             // 65536
#define OUT_ELEMS ((size_t)Bb*Ss*DM)

#define SCALE_L2E 0.18033688011112042f   // 0.125 * log2(e)

typedef unsigned int u32;
typedef unsigned short u16;
typedef unsigned long long u64;

// ---------------- device scratch ----------------
__device__ __half g_qi_h[MTOK*DM], g_qi_l[MTOK*DM];
__device__ __half g_ki_h[MTOK*DM], g_ki_l[MTOK*DM];
__device__ __half g_vi_h[MTOK*DM], g_vi_l[MTOK*DM];
__device__ __half g_wq_h[DM*DM], g_wq_l[DM*DM];
__device__ __half g_wk_h[DM*DM], g_wk_l[DM*DM];
__device__ __half g_wv_h[DM*DM], g_wv_l[DM*DM];
__device__ __half g_wo_h[DM*DM], g_wo_l[DM*DM];
__device__ __half g_qh_h[MTOK*DM], g_qh_l[MTOK*DM];
__device__ __half g_kh_h[MTOK*DM], g_kh_l[MTOK*DM];
__device__ __half g_vh_h[MTOK*DM], g_vh_l[MTOK*DM];
__device__ __half g_oh_h[MTOK*DM], g_oh_l[MTOK*DM];
__device__ float  g_y[MTOK*DM];
__device__ float  g_rinv[NROWS];
__device__ u64    g_mbits[(size_t)Bb*Ss*(Ss/64)];   // 1 bit per mask byte

// ---------------- helpers ----------------
__device__ __forceinline__ u32 smaddr(const void* p) {
    return (u32)__cvta_generic_to_shared(p);
}
__device__ __forceinline__ void ldsm4(u32& r0, u32& r1, u32& r2, u32& r3, u32 a) {
    asm volatile("ldmatrix.sync.aligned.m8n8.x4.shared.b16 {%0,%1,%2,%3},[%4];"
                 : "=r"(r0), "=r"(r1), "=r"(r2), "=r"(r3) : "r"(a));
}
__device__ __forceinline__ void ldsm4t(u32& r0, u32& r1, u32& r2, u32& r3, u32 a) {
    asm volatile("ldmatrix.sync.aligned.m8n8.x4.trans.shared.b16 {%0,%1,%2,%3},[%4];"
                 : "=r"(r0), "=r"(r1), "=r"(r2), "=r"(r3) : "r"(a));
}
__device__ __forceinline__ void mma16(float* d, const u32* a, u32 b0, u32 b1) {
    asm volatile(
        "mma.sync.aligned.m16n8k16.row.col.f32.f16.f16.f32 "
        "{%0,%1,%2,%3},{%4,%5,%6,%7},{%8,%9},{%0,%1,%2,%3};"
        : "+f"(d[0]), "+f"(d[1]), "+f"(d[2]), "+f"(d[3])
        : "r"(a[0]), "r"(a[1]), "r"(a[2]), "r"(a[3]), "r"(b0), "r"(b1));
}
__device__ __forceinline__ void cpa16(u32 dst, const void* src) {
    asm volatile("cp.async.cg.shared.global [%0], [%1], 16;" :: "r"(dst), "l"(src));
}
#define CP_COMMIT() asm volatile("cp.async.commit_group;")
#define CP_WAIT1()  asm volatile("cp.async.wait_group 1;")
#define CP_WAIT0()  asm volatile("cp.async.wait_group 0;")
__device__ __forceinline__ float ex2f(float x) {
    float r; asm("ex2.approx.f32 %0, %1;" : "=f"(r) : "f"(x)); return r;
}

// ---------------- mask -> bitmask (1 bit per byte) ----------------
__global__ void __launch_bounds__(256)
mask_bits(const unsigned char* __restrict__ mask)
{
    int i = blockIdx.x * 256 + threadIdx.x;       // < Bb*Ss*32
    const u64* src = (const u64*)(mask + (size_t)i * 64);
    u64 bits = 0;
    #pragma unroll
    for (int c = 0; c < 8; ++c) {
        u64 w = src[c] & 0x0101010101010101ULL;
        bits |= ((w * 0x0102040810204080ULL) >> 56) << (c * 8);
    }
    g_mbits[i] = bits;
}

// ---------------- split kernels ----------------
__global__ void __launch_bounds__(256)
split_f32(const float* __restrict__ src, __half* __restrict__ dh,
          __half* __restrict__ dl, int n4)
{
    int i = blockIdx.x * 256 + threadIdx.x;
    if (i >= n4) return;
    float4 v = ((const float4*)src)[i];
    __half2 h0 = __floats2half2_rn(v.x, v.y);
    __half2 h1 = __floats2half2_rn(v.z, v.w);
    float2 f0 = __half22float2(h0), f1 = __half22float2(h1);
    ((__half2*)dh)[2*i]   = h0; ((__half2*)dh)[2*i+1] = h1;
    ((__half2*)dl)[2*i]   = __floats2half2_rn(v.x - f0.x, v.y - f0.y);
    ((__half2*)dl)[2*i+1] = __floats2half2_rn(v.z - f1.x, v.w - f1.y);
}

// W[K][N] -> T[N][K] split hi/lo
__global__ void __launch_bounds__(256)
splitT_w(const float* __restrict__ W, __half* __restrict__ th,
         __half* __restrict__ tl)
{
    __shared__ float t[32][33];
    int kb = blockIdx.y * 32, nb = blockIdx.x * 32;
    int tx = threadIdx.x, ty = threadIdx.y;
    #pragma unroll
    for (int i = 0; i < 4; ++i)
        t[ty + i*8][tx] = W[(size_t)(kb + ty + i*8) * DM + nb + tx];
    __syncthreads();
    #pragma unroll
    for (int i = 0; i < 4; ++i) {
        int n = nb + ty + i*8, k = kb + tx;
        float v = t[tx][ty + i*8];
        __half h = __float2half_rn(v);
        th[(size_t)n * DM + k] = h;
        tl[(size_t)n * DM + k] = __float2half_rn(v - __half2float(h));
    }
}

// ---------------------------------------------------------------------------
// fp16 3-term GEMM, cp.async double-buffered.
// ---------------------------------------------------------------------------
#define SG 40
#define GARR (128*SG)
#define GSTG (4*GARR)
__global__ void __launch_bounds__(256)
gemm_h3(const __half* __restrict__ Ah, const __half* __restrict__ Al,
        const __half* __restrict__ Bh, const __half* __restrict__ Bl,
        const float* __restrict__ bias, const float* __restrict__ R,
        float omul,
        __half* __restrict__ Ch, __half* __restrict__ Cl,
        float* __restrict__ Cf, int M, int N, int K)
{
    extern __shared__ __half dsm[];
    const int tid = threadIdx.x, lane = tid & 31, wid = tid >> 5;
    const int wm = wid & 3, wn = wid >> 2;
    const int bm = blockIdx.y * 128, bn = blockIdx.x * 128;
    float acc[2][8][4] = {};
    const int arow = lane & 15, achk = lane >> 4;
    const int brow = ((lane >> 4) << 3) + (lane & 7), bchk = (lane >> 3) & 1;
    const u32 smbase = smaddr(dsm);

    auto load_stage = [&](int st, int k0) {
        u32 base = smbase + (u32)st * GSTG * 2;
        #pragma unroll
        for (int i = 0; i < 2; ++i) {
            int e = tid + i * 256;
            int m = e >> 2, c = e & 3;
            size_t ga = (size_t)(bm + m) * K + k0 + c*8;
            size_t gb = (size_t)(bn + m) * K + k0 + c*8;
            u32 o = (u32)(m*SG + c*8) * 2;
            cpa16(base + 0*GARR*2 + o, Ah + ga);
            cpa16(base + 1*GARR*2 + o, Al + ga);
            cpa16(base + 2*GARR*2 + o, Bh + gb);
            cpa16(base + 3*GARR*2 + o, Bl + gb);
        }
        CP_COMMIT();
    };

    const int nk = K / 32;
    load_stage(0, 0);
    for (int kt = 0; kt < nk; ++kt) {
        if (kt + 1 < nk) { load_stage((kt+1)&1, (kt+1)*32); CP_WAIT1(); }
        else             { CP_WAIT0(); }
        __syncthreads();
        const u32 sAh = smbase + (u32)(kt&1)*GSTG*2;
        const u32 sAl = sAh + GARR*2;
        const u32 sBh = sAl + GARR*2;
        const u32 sBl = sBh + GARR*2;
        #pragma unroll
        for (int kc = 0; kc < 2; ++kc) {
            u32 ah[2][4], al[2][4];
            #pragma unroll
            for (int mt = 0; mt < 2; ++mt) {
                int row = wm*32 + mt*16 + arow;
                u32 off = row*(SG*2) + (2*kc + achk)*16;
                ldsm4(ah[mt][0],ah[mt][1],ah[mt][2],ah[mt][3], sAh+off);
                ldsm4(al[mt][0],al[mt][1],al[mt][2],al[mt][3], sAl+off);
            }
            #pragma unroll
            for (int ntp = 0; ntp < 4; ++ntp) {
                int row = wn*64 + ntp*16 + brow;
                u32 off = row*(SG*2) + (2*kc + bchk)*16;
                u32 b0,b1,b2,b3, c0,c1,c2,c3;
                ldsm4(b0,b1,b2,b3, sBh+off);
                ldsm4(c0,c1,c2,c3, sBl+off);
                #pragma unroll
                for (int mt = 0; mt < 2; ++mt) {
                    mma16(acc[mt][2*ntp],   ah[mt], b0, b1);
                    mma16(acc[mt][2*ntp],   al[mt], b0, b1);
                    mma16(acc[mt][2*ntp],   ah[mt], c0, c1);
                    mma16(acc[mt][2*ntp+1], ah[mt], b2, b3);
                    mma16(acc[mt][2*ntp+1], al[mt], b2, b3);
                    mma16(acc[mt][2*ntp+1], ah[mt], c2, c3);
                }
            }
        }
        __syncthreads();
    }

    #pragma unroll
    for (int mt = 0; mt < 2; ++mt) {
        int r0 = bm + wm*32 + mt*16 + (lane >> 2);
        #pragma unroll
        for (int nt = 0; nt < 8; ++nt) {
            int n = bn + wn*64 + nt*8 + (lane & 3)*2;
            float2 bs = *(const float2*)&bias[n];
            float* d = acc[mt][nt];
            float v00 = (d[0]+bs.x)*omul, v01 = (d[1]+bs.y)*omul;
            float v10 = (d[2]+bs.x)*omul, v11 = (d[3]+bs.y)*omul;
            if (Cf) {
                float2 ra = *(const float2*)&R[(size_t)r0*N + n];
                float2 rb = *(const float2*)&R[(size_t)(r0+8)*N + n];
                *(float2*)&Cf[(size_t)r0*N + n]     = make_float2(v00+ra.x, v01+ra.y);
                *(float2*)&Cf[(size_t)(r0+8)*N + n] = make_float2(v10+rb.x, v11+rb.y);
            } else {
                __half2 h0 = __floats2half2_rn(v00, v01);
                __half2 h1 = __floats2half2_rn(v10, v11);
                float2 f0 = __half22float2(h0), f1 = __half22float2(h1);
                *(__half2*)&Ch[(size_t)r0*N + n]     = h0;
                *(__half2*)&Ch[(size_t)(r0+8)*N + n] = h1;
                *(__half2*)&Cl[(size_t)r0*N + n]     = __floats2half2_rn(v00-f0.x, v01-f0.y);
                *(__half2*)&Cl[(size_t)(r0+8)*N + n] = __floats2half2_rn(v10-f1.x, v11-f1.y);
            }
        }
    }
}

// ---------------------------------------------------------------------------
// Pass 1: row sums of 2^((qh+ql).kh) (masked). K hi-only staging.
// ---------------------------------------------------------------------------
#define SP 72
__global__ void __launch_bounds__(256)
attn_pass1()
{
    __shared__ __half sK[2][64*SP];
    const int tid = threadIdx.x, lane = tid & 31, wid = tid >> 5;
    const int bh = blockIdx.y, b = bh >> 4, h = bh & 15;
    const int bq = blockIdx.x * 128;
    const int arow = lane & 15, achk = lane >> 4;
    const int brow = ((lane >> 4) << 3) + (lane & 7), bchk = (lane >> 3) & 1;

    // Q fragments (hi in sK[0], lo in sK[1] staging)
    u32 qfh[4][4], qfl[4][4];
    #pragma unroll
    for (int c = 0; c < 2; ++c) {
        #pragma unroll
        for (int i = 0; i < 2; ++i) {
            int e = tid + i * 256;
            int m = e >> 3, ch = e & 7;
            size_t gq = (size_t)(b*Ss + bq + c*64 + m)*DM + h*DKh + ch*8;
            *(uint4*)&sK[0][m*SP + ch*8] = *(const uint4*)&g_qh_h[gq];
            *(uint4*)&sK[1][m*SP + ch*8] = *(const uint4*)&g_qh_l[gq];
        }
        __syncthreads();
        if ((wid >> 2) == c) {
            int rloc = (wid & 3)*16 + arow;
            #pragma unroll
            for (int kc = 0; kc < 4; ++kc) {
                u32 off = rloc*(SP*2) + (2*kc + achk)*16;
                ldsm4(qfh[kc][0],qfh[kc][1],qfh[kc][2],qfh[kc][3], smaddr(sK[0])+off);
                ldsm4(qfl[kc][0],qfl[kc][1],qfl[kc][2],qfl[kc][3], smaddr(sK[1])+off);
            }
        }
        __syncthreads();
    }

    auto load_stage = [&](int st, int kt) {
        #pragma unroll
        for (int i = 0; i < 2; ++i) {
            int e = tid + i * 256;
            int m = e >> 3, ch = e & 7;
            size_t gk = (size_t)(b*Ss + kt*64 + m)*DM + h*DKh + ch*8;
            cpa16(smaddr(sK[st]) + (u32)(m*SP + ch*8)*2, g_kh_h + gk);
        }
        CP_COMMIT();
    };

    const int r0 = bq + wid*16 + (lane >> 2);
    float rs0 = 0.f, rs1 = 0.f;

    load_stage(0, 0);
    for (int kt = 0; kt < 32; ++kt) {
        if (kt + 1 < 32) { load_stage((kt+1)&1, kt+1); CP_WAIT1(); }
        else             { CP_WAIT0(); }
        __syncthreads();
        const u32 sKh = smaddr(sK[kt&1]);

        float sf[8][4] = {};
        #pragma unroll
        for (int kc = 0; kc < 4; ++kc) {
            #pragma unroll
            for (int ntp = 0; ntp < 4; ++ntp) {
                int row = ntp*16 + brow;
                u32 off = row*(SP*2) + (2*kc + bchk)*16;
                u32 b0,b1,b2,b3;
                ldsm4(b0,b1,b2,b3, sKh+off);
                mma16(sf[2*ntp],   qfh[kc], b0, b1);
                mma16(sf[2*ntp],   qfl[kc], b0, b1);
                mma16(sf[2*ntp+1], qfh[kc], b2, b3);
                mma16(sf[2*ntp+1], qfl[kc], b2, b3);
            }
        }
        u64 mb0 = g_mbits[((size_t)b*Ss + r0)*32 + kt];
        u64 mb1 = g_mbits[((size_t)b*Ss + r0 + 8)*32 + kt];
        #pragma unroll
        for (int nt = 0; nt < 8; ++nt) {
            int sh = nt*8 + (lane & 3)*2;
            if (!((mb0 >> sh)     & 1)) rs0 += ex2f(sf[nt][0]);
            if (!((mb0 >> (sh+1)) & 1)) rs0 += ex2f(sf[nt][1]);
            if (!((mb1 >> sh)     & 1)) rs1 += ex2f(sf[nt][2]);
            if (!((mb1 >> (sh+1)) & 1)) rs1 += ex2f(sf[nt][3]);
        }
        __syncthreads();
    }

    rs0 += __shfl_xor_sync(0xffffffffu, rs0, 1);
    rs0 += __shfl_xor_sync(0xffffffffu, rs0, 2);
    rs1 += __shfl_xor_sync(0xffffffffu, rs1, 1);
    rs1 += __shfl_xor_sync(0xffffffffu, rs1, 2);
    if ((lane & 3) == 0) {
        g_rinv[(size_t)bh*Ss + r0]     = 1.0f / rs0;
        g_rinv[(size_t)bh*Ss + r0 + 8] = 1.0f / rs1;
    }
}

// ---------------------------------------------------------------------------
// Pass 2: S = (qh+ql).kh, p = 2^s*inv -> attn write; PV = p16 @ Vh fused.
// ---------------------------------------------------------------------------
__global__ void __launch_bounds__(256)
attn_pass2(float* __restrict__ P)
{
    __shared__ __half sKV[2][2][64*SP];   // [stage][K/V]
    const int tid = threadIdx.x, lane = tid & 31, wid = tid >> 5;
    const int bh = blockIdx.y, b = bh >> 4, h = bh & 15;
    const int bq = blockIdx.x * 128;
    const int arow = lane & 15, achk = lane >> 4;
    const int brow = ((lane >> 4) << 3) + (lane & 7), bchk = (lane >> 3) & 1;

    // Q fragments (stage via sKV[0][0]/sKV[0][1])
    u32 qfh[4][4], qfl[4][4];
    #pragma unroll
    for (int c = 0; c < 2; ++c) {
        #pragma unroll
        for (int i = 0; i < 2; ++i) {
            int e = tid + i * 256;
            int m = e >> 3, ch = e & 7;
            size_t gq = (size_t)(b*Ss + bq + c*64 + m)*DM + h*DKh + ch*8;
            *(uint4*)&sKV[0][0][m*SP + ch*8] = *(const uint4*)&g_qh_h[gq];
            *(uint4*)&sKV[0][1][m*SP + ch*8] = *(const uint4*)&g_qh_l[gq];
        }
        __syncthreads();
        if ((wid >> 2) == c) {
            int rloc = (wid & 3)*16 + arow;
            #pragma unroll
            for (int kc = 0; kc < 4; ++kc) {
                u32 off = rloc*(SP*2) + (2*kc + achk)*16;
                ldsm4(qfh[kc][0],qfh[kc][1],qfh[kc][2],qfh[kc][3], smaddr(sKV[0][0])+off);
                ldsm4(qfl[kc][0],qfl[kc][1],qfl[kc][2],qfl[kc][3], smaddr(sKV[0][1])+off);
            }
        }
        __syncthreads();
    }

    auto load_stage = [&](int st, int kt) {
        #pragma unroll
        for (int i = 0; i < 2; ++i) {
            int e = tid + i * 256;
            int m = e >> 3, ch = e & 7;
            size_t gk = (size_t)(b*Ss + kt*64 + m)*DM + h*DKh + ch*8;
            u32 o = (u32)(m*SP + ch*8)*2;
            cpa16(smaddr(sKV[st][0]) + o, g_kh_h + gk);
            cpa16(smaddr(sKV[st][1]) + o, g_vh_h + gk);
        }
        CP_COMMIT();
    };

    const int r0 = bq + wid*16 + (lane >> 2);
    const float inv0 = g_rinv[(size_t)bh*Ss + r0];
    const float inv1 = g_rinv[(size_t)bh*Ss + r0 + 8];
    float oacc[8][4] = {};

    load_stage(0, 0);
    for (int kt = 0; kt < 32; ++kt) {
        if (kt + 1 < 32) { load_stage((kt+1)&1, kt+1); CP_WAIT1(); }
        else             { CP_WAIT0(); }
        __syncthreads();
        const u32 sKh = smaddr(sKV[kt&1][0]);
        const u32 sVh = smaddr(sKV[kt&1][1]);

        // S = (qh+ql).kh
        float sf[8][4] = {};
        #pragma unroll
        for (int kc = 0; kc < 4; ++kc) {
            #pragma unroll
            for (int ntp = 0; ntp < 4; ++ntp) {
                int row = ntp*16 + brow;
                u32 off = row*(SP*2) + (2*kc + bchk)*16;
                u32 b0,b1,b2,b3;
                ldsm4(b0,b1,b2,b3, sKh+off);
                mma16(sf[2*ntp],   qfh[kc], b0, b1);
                mma16(sf[2*ntp],   qfl[kc], b0, b1);
                mma16(sf[2*ntp+1], qfh[kc], b2, b3);
                mma16(sf[2*ntp+1], qfl[kc], b2, b3);
            }
        }

        // p = 2^s * inv (masked), write final attn
        u64 mb0 = g_mbits[((size_t)b*Ss + r0)*32 + kt];
        u64 mb1 = g_mbits[((size_t)b*Ss + r0 + 8)*32 + kt];
        #pragma unroll
        for (int nt = 0; nt < 8; ++nt) {
            int sh = nt*8 + (lane & 3)*2;
            int col = kt*64 + sh;
            float p0 = ((mb0 >> sh)     & 1) ? 0.f : ex2f(sf[nt][0]) * inv0;
            float p1 = ((mb0 >> (sh+1)) & 1) ? 0.f : ex2f(sf[nt][1]) * inv0;
            float p2 = ((mb1 >> sh)     & 1) ? 0.f : ex2f(sf[nt][2]) * inv1;
            float p3 = ((mb1 >> (sh+1)) & 1) ? 0.f : ex2f(sf[nt][3]) * inv1;
            *(float2*)&P[((size_t)bh*Ss + r0)*Ss + col]     = make_float2(p0, p1);
            *(float2*)&P[((size_t)bh*Ss + r0 + 8)*Ss + col] = make_float2(p2, p3);
            sf[nt][0] = p0; sf[nt][1] = p1; sf[nt][2] = p2; sf[nt][3] = p3;
        }

        // PV: O += p16 @ Vh
        #pragma unroll
        for (int kc2 = 0; kc2 < 4; ++kc2) {
            u32 aph[4];
            #pragma unroll
            for (int half_ = 0; half_ < 2; ++half_) {
                float* f = sf[2*kc2 + half_];
                __half2 h0 = __floats2half2_rn(f[0], f[1]);
                __half2 h1 = __floats2half2_rn(f[2], f[3]);
                aph[2*half_]   = *(u32*)&h0;
                aph[2*half_+1] = *(u32*)&h1;
            }
            #pragma unroll
            for (int ntv = 0; ntv < 4; ++ntv) {
                int vrow = kc2*16 + ((lane >> 3) & 1)*8 + (lane & 7);
                int dch  = ntv*16 + (lane >> 4)*8;
                u32 off = vrow*(SP*2) + dch*2;
                u32 b0,b1,b2,b3;
                ldsm4t(b0,b1,b2,b3, sVh+off);
                mma16(oacc[2*ntv],   aph, b0, b1);
                mma16(oacc[2*ntv+1], aph, b2, b3);
            }
        }
        __syncthreads();
    }

    #pragma unroll
    for (int nt = 0; nt < 8; ++nt) {
        int d = nt*8 + (lane & 3)*2;
        size_t i0 = (size_t)(b*Ss + r0)*DM + h*DKh + d;
        size_t i1 = (size_t)(b*Ss + r0 + 8)*DM + h*DKh + d;
        __half2 h0 = __floats2half2_rn(oacc[nt][0], oacc[nt][1]);
        __half2 h1 = __floats2half2_rn(oacc[nt][2], oacc[nt][3]);
        float2 f0 = __half22float2(h0), f1 = __half22float2(h1);
        *(__half2*)&g_oh_h[i0] = h0;
        *(__half2*)&g_oh_h[i1] = h1;
        *(__half2*)&g_oh_l[i0] = __floats2half2_rn(oacc[nt][0]-f0.x, oacc[nt][1]-f0.y);
        *(__half2*)&g_oh_l[i1] = __floats2half2_rn(oacc[nt][2]-f1.x, oacc[nt][3]-f1.y);
    }
}

// ---------------------------------------------------------------------------
// LayerNorm per row of 1024
// ---------------------------------------------------------------------------
__global__ void __launch_bounds__(256)
layernorm(const float* __restrict__ Xin, const float* __restrict__ gamma,
          const float* __restrict__ beta, float* __restrict__ out)
{
    const float* x = Xin + (size_t)blockIdx.x * DM;
    float* o = out + (size_t)blockIdx.x * DM;
    const int tid = threadIdx.x;
    __shared__ float r1[256], r2[256];

    float v[4], s = 0.f, sq = 0.f;
    #pragma unroll
    for (int i = 0; i < 4; ++i) {
        v[i] = x[tid + i * 256];
        s += v[i];
        sq += v[i] * v[i];
    }
    r1[tid] = s; r2[tid] = sq; __syncthreads();
    for (int st = 128; st > 0; st >>= 1) {
        if (tid < st) { r1[tid] += r1[tid + st]; r2[tid] += r2[tid + st]; }
        __syncthreads();
    }
    float mean = r1[0] * (1.0f / DM);
    float var  = r2[0] * (1.0f / DM) - mean * mean;
    float inv = rsqrtf(var + 1e-5f);
    #pragma unroll
    for (int i = 0; i < 4; ++i) {
        int c = tid + i * 256;
        o[c] = (v[i] - mean) * inv * gamma[c] + beta[c];
    }
}

// ---------------------------------------------------------------------------
extern "C" void kernel_launch(void* const* d_in, const int* in_sizes, int n_in,
                              void* d_out, int out_size)
{
    const float* q    = (const float*)d_in[0];
    const float* k    = (const float*)d_in[1];
    const float* v    = (const float*)d_in[2];
    const unsigned char* mask = (const unsigned char*)d_in[3];
    const float* Wq   = (const float*)d_in[4];
    const float* bq   = (const float*)d_in[5];
    const float* Wk   = (const float*)d_in[6];
    const float* bk   = (const float*)d_in[7];
    const float* Wv   = (const float*)d_in[8];
    const float* bv   = (const float*)d_in[9];
    const float* Wo   = (const float*)d_in[10];
    const float* bo   = (const float*)d_in[11];
    const float* ln_g = (const float*)d_in[12];
    const float* ln_b = (const float*)d_in[13];

    float* outp = (float*)d_out;
    float* attn = outp + OUT_ELEMS;

    __half *qi_h,*qi_l,*ki_h,*ki_l,*vi_h,*vi_l;
    __half *wq_h,*wq_l,*wk_h,*wk_l,*wv_h,*wv_l,*wo_h,*wo_l;
    __half *qh_h,*qh_l,*kh_h,*kh_l,*vh_h,*vh_l,*oh_h,*oh_l;
    float *y;
    cudaGetSymbolAddress((void**)&qi_h, g_qi_h); cudaGetSymbolAddress((void**)&qi_l, g_qi_l);
    cudaGetSymbolAddress((void**)&ki_h, g_ki_h); cudaGetSymbolAddress((void**)&ki_l, g_ki_l);
    cudaGetSymbolAddress((void**)&vi_h, g_vi_h); cudaGetSymbolAddress((void**)&vi_l, g_vi_l);
    cudaGetSymbolAddress((void**)&wq_h, g_wq_h); cudaGetSymbolAddress((void**)&wq_l, g_wq_l);
    cudaGetSymbolAddress((void**)&wk_h, g_wk_h); cudaGetSymbolAddress((void**)&wk_l, g_wk_l);
    cudaGetSymbolAddress((void**)&wv_h, g_wv_h); cudaGetSymbolAddress((void**)&wv_l, g_wv_l);
    cudaGetSymbolAddress((void**)&wo_h, g_wo_h); cudaGetSymbolAddress((void**)&wo_l, g_wo_l);
    cudaGetSymbolAddress((void**)&qh_h, g_qh_h); cudaGetSymbolAddress((void**)&qh_l, g_qh_l);
    cudaGetSymbolAddress((void**)&kh_h, g_kh_h); cudaGetSymbolAddress((void**)&kh_l, g_kh_l);
    cudaGetSymbolAddress((void**)&vh_h, g_vh_h); cudaGetSymbolAddress((void**)&vh_l, g_vh_l);
    cudaGetSymbolAddress((void**)&oh_h, g_oh_h); cudaGetSymbolAddress((void**)&oh_l, g_oh_l);
    cudaGetSymbolAddress((void**)&y, g_y);

    static bool attr_done = false;
    const int GEMM_SMEM = 2 * GSTG * 2;
    if (!attr_done) {
        cudaFuncSetAttribute(gemm_h3, cudaFuncAttributeMaxDynamicSharedMemorySize, GEMM_SMEM);
        attr_done = true;
    }

    const int n4 = MTOK * DM / 4;
    split_f32<<<(n4+255)/256, 256>>>(q, qi_h, qi_l, n4);
    split_f32<<<(n4+255)/256, 256>>>(k, ki_h, ki_l, n4);
    split_f32<<<(n4+255)/256, 256>>>(v, vi_h, vi_l, n4);
    mask_bits<<<(Bb*Ss*32)/256, 256>>>(mask);

    dim3 gT(DM/32, DM/32), bT(32, 8);
    splitT_w<<<gT, bT>>>(Wq, wq_h, wq_l);
    splitT_w<<<gT, bT>>>(Wk, wk_h, wk_l);
    splitT_w<<<gT, bT>>>(Wv, wv_h, wv_l);
    splitT_w<<<gT, bT>>>(Wo, wo_h, wo_l);

    dim3 gProj(DM/128, MTOK/128);   // (8, 32)
    gemm_h3<<<gProj, 256, GEMM_SMEM>>>(qi_h, qi_l, wq_h, wq_l, bq, nullptr,
                                       SCALE_L2E, qh_h, qh_l, nullptr, MTOK, DM, DM);
    gemm_h3<<<gProj, 256, GEMM_SMEM>>>(ki_h, ki_l, wk_h, wk_l, bk, nullptr,
                                       1.0f, kh_h, kh_l, nullptr, MTOK, DM, DM);
    gemm_h3<<<gProj, 256, GEMM_SMEM>>>(vi_h, vi_l, wv_h, wv_l, bv, nullptr,
                                       1.0f, vh_h, vh_l, nullptr, MTOK, DM, DM);

    dim3 gAttn(Ss/128, Bb*Hh);      // (16, 32)
    attn_pass1<<<gAttn, 256>>>();
    attn_pass2<<<gAttn, 256>>>(attn);

    gemm_h3<<<gProj, 256, GEMM_SMEM>>>(oh_h, oh_l, wo_h, wo_l, bo, q,
                                       1.0f, nullptr, nullptr, y, MTOK, DM, DM);

    layernorm<<<MTOK, 256>>>(y, ln_g, ln_b, outp);
}